// round 2
// baseline (speedup 1.0000x reference)
#include <cuda_runtime.h>
#include <math.h>

#define SEQ   2048
#define HID   4096
#define HEADS 32
#define HDIM  128
#define QKVN  12288

// ---- scratch (device globals; no runtime allocation allowed) ----
__device__ float g_proj[(size_t)SEQ * QKVN];   // qkv projection [s, 3*HID]
__device__ float g_attn[(size_t)SEQ * HID];    // attention output [s, HID]
__device__ float g_cos[SEQ * 64];
__device__ float g_sin[SEQ * 64];

__device__ __forceinline__ float neg_inf() { return __int_as_float(0xff800000); }

// ---------------- RoPE tables (fp64 for accuracy) ----------------
__global__ void rope_tables_kernel(const int* __restrict__ pos_ids) {
    int s = blockIdx.x;
    int d = threadIdx.x;                       // 0..63
    double inv = pow(10000.0, -(double)(2 * d) / 128.0);
    double ang = (double)pos_ids[s] * inv;
    g_cos[s * 64 + d] = (float)cos(ang);
    g_sin[s * 64 + d] = (float)sin(ang);
}

// ---------------- fused dequant SGEMM ----------------
// C[M,N] = A[M,K] @ W, W[k,n] = (Qw[k,n] - Zr[k/128,n]) * Sc[k/128,n]
// 128x128 block tile, BK=16, 256 threads, 8x8 per thread (4+4 quadrant split)
__global__ __launch_bounds__(256)
void gemm_dequant_kernel(const float* __restrict__ A,
                         const int*   __restrict__ Qw,
                         const float* __restrict__ Sc,
                         const float* __restrict__ Zr,
                         float*       __restrict__ C,
                         int M, int N, int K) {
    __shared__ float As[16][128];   // transposed A tile: As[k][m]
    __shared__ float Bs[16][128];   // dequantized B tile: Bs[k][n]
    const int tid = threadIdx.x;
    const int tx = tid & 15, ty = tid >> 4;
    const int m0 = blockIdx.y << 7, n0 = blockIdx.x << 7;

    float acc[8][8];
    #pragma unroll
    for (int i = 0; i < 8; i++)
        #pragma unroll
        for (int j = 0; j < 8; j++) acc[i][j] = 0.f;

    for (int k0 = 0; k0 < K; k0 += 16) {
        // ---- load A tile (128 rows x 16 k), store transposed ----
        #pragma unroll
        for (int t = 0; t < 2; t++) {
            int idx = tid + t * 256;           // 0..511
            int r = idx >> 2;                  // 0..127
            int c = (idx & 3) << 2;            // 0,4,8,12
            float4 v = *(const float4*)(A + (size_t)(m0 + r) * K + k0 + c);
            As[c + 0][r] = v.x; As[c + 1][r] = v.y;
            As[c + 2][r] = v.z; As[c + 3][r] = v.w;
        }
        // ---- load B tile (16 k x 128 n) with fused dequant ----
        int g = k0 >> 7;                        // AWQ group (GROUP=128, BK=16 divides)
        #pragma unroll
        for (int t = 0; t < 2; t++) {
            int idx = tid + t * 256;
            int r = idx >> 5;                   // 0..15
            int c = (idx & 31) << 2;            // 0..124
            int4   q = *(const int4*)(Qw + (size_t)(k0 + r) * N + n0 + c);
            float4 s = *(const float4*)(Sc + (size_t)g * N + n0 + c);
            float4 z = *(const float4*)(Zr + (size_t)g * N + n0 + c);
            Bs[r][c + 0] = ((float)q.x - z.x) * s.x;
            Bs[r][c + 1] = ((float)q.y - z.y) * s.y;
            Bs[r][c + 2] = ((float)q.z - z.z) * s.z;
            Bs[r][c + 3] = ((float)q.w - z.w) * s.w;
        }
        __syncthreads();
        #pragma unroll
        for (int kk = 0; kk < 16; kk++) {
            float a[8], b[8];
            *(float4*)&a[0] = *(const float4*)&As[kk][ty * 4];
            *(float4*)&a[4] = *(const float4*)&As[kk][64 + ty * 4];
            *(float4*)&b[0] = *(const float4*)&Bs[kk][tx * 4];
            *(float4*)&b[4] = *(const float4*)&Bs[kk][64 + tx * 4];
            #pragma unroll
            for (int i = 0; i < 8; i++)
                #pragma unroll
                for (int j = 0; j < 8; j++)
                    acc[i][j] += a[i] * b[j];
        }
        __syncthreads();
    }
    // ---- store (quadrant mapping) ----
    #pragma unroll
    for (int i = 0; i < 8; i++) {
        int r = m0 + ((i < 4) ? (ty * 4 + i) : (64 + ty * 4 + (i - 4)));
        float4 v0 = make_float4(acc[i][0], acc[i][1], acc[i][2], acc[i][3]);
        float4 v1 = make_float4(acc[i][4], acc[i][5], acc[i][6], acc[i][7]);
        *(float4*)(C + (size_t)r * N + n0 + tx * 4)      = v0;
        *(float4*)(C + (size_t)r * N + n0 + 64 + tx * 4) = v1;
    }
}

// ---------------- RoPE apply (in-place on q and k sections) ----------------
__global__ void rope_apply_kernel() {
    int s = blockIdx.x;
    int w = blockIdx.y;                       // 0 = q section, 1 = k section
    float* base = g_proj + (size_t)s * QKVN + w * HID;
    for (int i = threadIdx.x; i < HEADS * 64; i += blockDim.x) {
        int h = i >> 6, d = i & 63;
        float c  = g_cos[s * 64 + d];
        float sn = g_sin[s * 64 + d];
        float x1 = base[h * 128 + d];
        float x2 = base[h * 128 + d + 64];
        base[h * 128 + d]      = x1 * c - x2 * sn;  // x1*cos + (-x2)*sin
        base[h * 128 + d + 64] = x2 * c + x1 * sn;  // x2*cos + ( x1)*sin
    }
}

// ---------------- fp32 flash attention (causal) ----------------
// block = (qt, head). 256 threads: tx=tid&15 (col/d groups), ty=tid>>4 (row group).
// Tile: 64 q-rows x 64 kv-cols; per thread: 4 rows, 4 score cols (tx+16j),
// O accumulators for 8 d-columns (tx+16j, j=0..7).
__global__ __launch_bounds__(256)
void flash_attn_kernel(float* __restrict__ out) {
    extern __shared__ float sm[];
    float* Qs = sm;                    // [64][129]
    float* Ks = sm + 64 * 129;         // [64][129]
    float* Vs = sm + 2 * 64 * 129;     // [64][129]
    float* Ps = sm + 3 * 64 * 129;     // [64][68]
    const int qt = blockIdx.x, h = blockIdx.y;
    const int tid = threadIdx.x;
    const int tx = tid & 15, ty = tid >> 4;
    const float* qb = g_proj + (size_t)h * HDIM;
    const float* kb = g_proj + HID + (size_t)h * HDIM;
    const float* vb = g_proj + 2 * HID + (size_t)h * HDIM;
    const float scale = 0.08838834764831845f;   // 1/sqrt(128)

    // load Q tile (64 x 128)
    for (int idx = tid; idx < 64 * 32; idx += 256) {
        int r = idx >> 5, c = (idx & 31) << 2;
        float4 v = *(const float4*)(qb + (size_t)(qt * 64 + r) * QKVN + c);
        Qs[r * 129 + c]     = v.x; Qs[r * 129 + c + 1] = v.y;
        Qs[r * 129 + c + 2] = v.z; Qs[r * 129 + c + 3] = v.w;
    }

    float m[4], l[4], Oa[4][8];
    #pragma unroll
    for (int i = 0; i < 4; i++) {
        m[i] = neg_inf(); l[i] = 0.f;
        #pragma unroll
        for (int j = 0; j < 8; j++) Oa[i][j] = 0.f;
    }

    for (int kt = 0; kt <= qt; kt++) {
        __syncthreads();   // protect Ks/Vs from previous iteration's readers
        for (int idx = tid; idx < 64 * 32; idx += 256) {
            int r = idx >> 5, c = (idx & 31) << 2;
            float4 kv = *(const float4*)(kb + (size_t)(kt * 64 + r) * QKVN + c);
            Ks[r * 129 + c]     = kv.x; Ks[r * 129 + c + 1] = kv.y;
            Ks[r * 129 + c + 2] = kv.z; Ks[r * 129 + c + 3] = kv.w;
            float4 vv = *(const float4*)(vb + (size_t)(kt * 64 + r) * QKVN + c);
            Vs[r * 129 + c]     = vv.x; Vs[r * 129 + c + 1] = vv.y;
            Vs[r * 129 + c + 2] = vv.z; Vs[r * 129 + c + 3] = vv.w;
        }
        __syncthreads();

        // ---- S = Q K^T (per-thread 4x4) ----
        float s4[4][4];
        #pragma unroll
        for (int i = 0; i < 4; i++)
            #pragma unroll
            for (int j = 0; j < 4; j++) s4[i][j] = 0.f;
        #pragma unroll 8
        for (int d = 0; d < 128; d++) {
            float q0 = Qs[(ty * 4 + 0) * 129 + d];
            float q1 = Qs[(ty * 4 + 1) * 129 + d];
            float q2 = Qs[(ty * 4 + 2) * 129 + d];
            float q3 = Qs[(ty * 4 + 3) * 129 + d];
            float k0 = Ks[(tx +  0) * 129 + d];
            float k1 = Ks[(tx + 16) * 129 + d];
            float k2 = Ks[(tx + 32) * 129 + d];
            float k3 = Ks[(tx + 48) * 129 + d];
            s4[0][0] += q0 * k0; s4[0][1] += q0 * k1; s4[0][2] += q0 * k2; s4[0][3] += q0 * k3;
            s4[1][0] += q1 * k0; s4[1][1] += q1 * k1; s4[1][2] += q1 * k2; s4[1][3] += q1 * k3;
            s4[2][0] += q2 * k0; s4[2][1] += q2 * k1; s4[2][2] += q2 * k2; s4[2][3] += q2 * k3;
            s4[3][0] += q3 * k0; s4[3][1] += q3 * k1; s4[3][2] += q3 * k2; s4[3][3] += q3 * k3;
        }

        // ---- online softmax update ----
        #pragma unroll
        for (int i = 0; i < 4; i++) {
            int row = qt * 64 + ty * 4 + i;
            float tm = neg_inf();
            #pragma unroll
            for (int j = 0; j < 4; j++) {
                int col = kt * 64 + tx + 16 * j;
                float v = (col <= row) ? s4[i][j] * scale : neg_inf();
                s4[i][j] = v;
                tm = fmaxf(tm, v);
            }
            #pragma unroll
            for (int o = 8; o; o >>= 1)
                tm = fmaxf(tm, __shfl_xor_sync(0xffffffffu, tm, o));
            float mn = fmaxf(m[i], tm);          // finite after reduction
            float alpha = __expf(m[i] - mn);     // exp(-inf)=0 on first tile
            float rs = 0.f;
            #pragma unroll
            for (int j = 0; j < 4; j++) {
                float p = __expf(s4[i][j] - mn); // masked -> exp(-inf)=0
                rs += p;
                Ps[(ty * 4 + i) * 68 + tx + 16 * j] = p;
            }
            #pragma unroll
            for (int o = 8; o; o >>= 1)
                rs += __shfl_xor_sync(0xffffffffu, rs, o);
            l[i] = l[i] * alpha + rs;
            m[i] = mn;
            #pragma unroll
            for (int j = 0; j < 8; j++) Oa[i][j] *= alpha;
        }
        __syncthreads();   // Ps visible to all

        // ---- O += P V ----
        #pragma unroll 4
        for (int c = 0; c < 64; c++) {
            float p0 = Ps[(ty * 4 + 0) * 68 + c];
            float p1 = Ps[(ty * 4 + 1) * 68 + c];
            float p2 = Ps[(ty * 4 + 2) * 68 + c];
            float p3 = Ps[(ty * 4 + 3) * 68 + c];
            #pragma unroll
            for (int j = 0; j < 8; j++) {
                float v = Vs[c * 129 + tx + 16 * j];
                Oa[0][j] += p0 * v;
                Oa[1][j] += p1 * v;
                Oa[2][j] += p2 * v;
                Oa[3][j] += p3 * v;
            }
        }
    }

    // ---- epilogue: O / l -> attn buffer [s, h*128 + d] ----
    #pragma unroll
    for (int i = 0; i < 4; i++) {
        float inv = 1.f / l[i];
        int row = qt * 64 + ty * 4 + i;
        #pragma unroll
        for (int j = 0; j < 8; j++)
            out[(size_t)row * HID + h * HDIM + tx + 16 * j] = Oa[i][j] * inv;
    }
}

extern "C" void kernel_launch(void* const* d_in, const int* in_sizes, int n_in,
                              void* d_out, int out_size) {
    const float* hidden = (const float*)d_in[0];
    const int*   pos    = (const int*)d_in[1];
    const int*   qkv_qw = (const int*)d_in[2];
    const float* qkv_s  = (const float*)d_in[3];
    const float* qkv_z  = (const float*)d_in[4];
    const int*   o_qw   = (const int*)d_in[5];
    const float* o_s    = (const float*)d_in[6];
    const float* o_z    = (const float*)d_in[7];
    float* out = (float*)d_out;

    void* p;
    cudaGetSymbolAddress(&p, g_proj); float* proj = (float*)p;
    cudaGetSymbolAddress(&p, g_attn); float* attn = (float*)p;

    // 1. RoPE cos/sin tables
    rope_tables_kernel<<<SEQ, 64>>>(pos);

    // 2. QKV projection with fused AWQ dequant
    gemm_dequant_kernel<<<dim3(QKVN / 128, SEQ / 128), 256>>>(
        hidden, qkv_qw, qkv_s, qkv_z, proj, SEQ, QKVN, HID);

    // 3. RoPE on q and k
    rope_apply_kernel<<<dim3(SEQ, 2), 256>>>();

    // 4. causal flash attention
    int smem = (3 * 64 * 129 + 64 * 68) * (int)sizeof(float);  // 116480 B
    cudaFuncSetAttribute(flash_attn_kernel,
                         cudaFuncAttributeMaxDynamicSharedMemorySize, smem);
    flash_attn_kernel<<<dim3(SEQ / 64, HEADS), 256, smem>>>(attn);

    // 5. output projection with fused AWQ dequant
    gemm_dequant_kernel<<<dim3(HID / 128, SEQ / 128), 256>>>(
        attn, o_qw, o_s, o_z, out, SEQ, HID, HID);
}

// round 4
// speedup vs baseline: 1.8933x; 1.8933x over previous
#include <cuda_runtime.h>
#include <cuda_bf16.h>
#include <math.h>
#include <stdint.h>

#define SEQ   2048
#define HID   4096
#define HEADS 32
#define HDIM  128
#define QKVN  12288

// ---------------- scratch (device globals; no runtime allocation) ----------------
__device__ float g_proj[(size_t)SEQ * QKVN];                 // qkv projection [s, 3*HID]
__device__ float g_attn[(size_t)SEQ * HID];                  // attention output [s, HID]
__device__ float g_cos[SEQ * 64];
__device__ float g_sin[SEQ * 64];
__device__ __nv_bfloat16 g_ah[(size_t)SEQ * HID];            // activation hi
__device__ __nv_bfloat16 g_al[(size_t)SEQ * HID];            // activation lo
__device__ __nv_bfloat16 g_bh[(size_t)QKVN * HID];           // weight^T hi [N,K] (reused for O)
__device__ __nv_bfloat16 g_bl[(size_t)QKVN * HID];           // weight^T lo [N,K]

__device__ __forceinline__ float neg_inf() { return __int_as_float(0xff800000); }

__device__ __forceinline__ uint32_t smem_to_u32(const void* p) {
    uint32_t a;
    asm("{ .reg .u64 t; cvta.to.shared.u64 t, %1; cvt.u32.u64 %0, t; }" : "=r"(a) : "l"(p));
    return a;
}
__device__ __forceinline__ void cp_async16(uint32_t dst, const void* src) {
    asm volatile("cp.async.cg.shared.global [%0], [%1], 16;" :: "r"(dst), "l"(src));
}
#define CP_COMMIT() asm volatile("cp.async.commit_group;" ::: "memory")
#define CP_WAIT(n)  asm volatile("cp.async.wait_group %0;" :: "n"(n) : "memory")

#define LDSM_X4(r, a) \
    asm volatile("ldmatrix.sync.aligned.m8n8.x4.shared.b16 {%0,%1,%2,%3}, [%4];" \
        : "=r"((r)[0]), "=r"((r)[1]), "=r"((r)[2]), "=r"((r)[3]) : "r"(a))
#define LDSM_X2(r, a) \
    asm volatile("ldmatrix.sync.aligned.m8n8.x2.shared.b16 {%0,%1}, [%2];" \
        : "=r"((r)[0]), "=r"((r)[1]) : "r"(a))
#define MMA_BF16(d, a, b) \
    asm volatile("mma.sync.aligned.m16n8k16.row.col.f32.bf16.bf16.f32 " \
        "{%0,%1,%2,%3}, {%4,%5,%6,%7}, {%8,%9}, {%0,%1,%2,%3};" \
        : "+f"((d)[0]), "+f"((d)[1]), "+f"((d)[2]), "+f"((d)[3]) \
        : "r"((a)[0]), "r"((a)[1]), "r"((a)[2]), "r"((a)[3]), "r"((b)[0]), "r"((b)[1]))

// smem tile: 128 rows x 64 bytes (32 bf16). 16B segment XOR-swizzle:
// seg' = seg ^ ((row>>1)&3) -> conflict-free for 16B stores and ldmatrix phases.
__device__ __forceinline__ uint32_t swz(int r, int kbyte) {
    uint32_t seg = ((uint32_t)(kbyte >> 4)) ^ (((uint32_t)r >> 1) & 3u);
    return (uint32_t)r * 64u + (seg << 4) + (uint32_t)(kbyte & 15);
}

// ---------------- RoPE tables (fp64 for accuracy) ----------------
__global__ void rope_tables_kernel(const int* __restrict__ pos_ids) {
    int s = blockIdx.x;
    int d = threadIdx.x;                       // 0..63
    double inv = pow(10000.0, -(double)(2 * d) / 128.0);
    double ang = (double)pos_ids[s] * inv;
    g_cos[s * 64 + d] = (float)cos(ang);
    g_sin[s * 64 + d] = (float)sin(ang);
}

// ---------------- fp32 -> bf16 hi/lo split ----------------
__global__ __launch_bounds__(256)
void split_kernel(const float* __restrict__ X, __nv_bfloat16* __restrict__ H,
                  __nv_bfloat16* __restrict__ L) {
    int i = (blockIdx.x * 256 + threadIdx.x) * 4;
    float4 v = *(const float4*)(X + i);
    __nv_bfloat16 h0 = __float2bfloat16(v.x), h1 = __float2bfloat16(v.y);
    __nv_bfloat16 h2 = __float2bfloat16(v.z), h3 = __float2bfloat16(v.w);
    H[i + 0] = h0; H[i + 1] = h1; H[i + 2] = h2; H[i + 3] = h3;
    L[i + 0] = __float2bfloat16(v.x - __bfloat162float(h0));
    L[i + 1] = __float2bfloat16(v.y - __bfloat162float(h1));
    L[i + 2] = __float2bfloat16(v.z - __bfloat162float(h2));
    L[i + 3] = __float2bfloat16(v.w - __bfloat162float(h3));
}

// ---------------- dequant + transpose: W[k,n] -> B[n,k] bf16 hi/lo ----------------
__global__ __launch_bounds__(256)
void dequant_transpose_kernel(const int* __restrict__ Qw, const float* __restrict__ Sc,
                              const float* __restrict__ Zr, __nv_bfloat16* __restrict__ Bh,
                              __nv_bfloat16* __restrict__ Bl, int K, int N) {
    __shared__ float w[32][33];
    int n0 = blockIdx.x * 32, k0 = blockIdx.y * 32;
    int tx = threadIdx.x & 31, ty = threadIdx.x >> 5;     // 32 x 8
    int g = k0 >> 7;                                      // GROUP=128, 32 | 128
    float s = Sc[(size_t)g * N + n0 + tx];
    float z = Zr[(size_t)g * N + n0 + tx];
    #pragma unroll
    for (int rr = 0; rr < 32; rr += 8) {
        int q = Qw[(size_t)(k0 + rr + ty) * N + n0 + tx];
        w[rr + ty][tx] = ((float)q - z) * s;
    }
    __syncthreads();
    #pragma unroll
    for (int rr = 0; rr < 32; rr += 8) {
        int n = rr + ty;
        float v = w[tx][n];
        __nv_bfloat16 h = __float2bfloat16(v);
        size_t o = (size_t)(n0 + n) * K + k0 + tx;
        Bh[o] = h;
        Bl[o] = __float2bfloat16(v - __bfloat162float(h));
    }
}

// ---------------- bf16x3 mma.sync GEMM ----------------
// C[M,N] = Ah@Bh^T + Al@Bh^T + Ah@Bl^T   (A:[M,K], B:[N,K], fp32 acc)
// CTA 128x128, BK=32, 256 threads = 8 warps (2m x 4n), warp tile 64x32.
#define ST_AH 0
#define ST_AL 8192
#define ST_BH 16384
#define ST_BL 24576
#define STAGE_BYTES 32768

__global__ __launch_bounds__(256, 1)
void gemm_mma_kernel(const __nv_bfloat16* __restrict__ Ah,
                     const __nv_bfloat16* __restrict__ Al,
                     const __nv_bfloat16* __restrict__ Bh,
                     const __nv_bfloat16* __restrict__ Bl,
                     float* __restrict__ C, int M, int N, int K) {
    extern __shared__ char smraw[];
    const uint32_t sb = smem_to_u32(smraw);
    const int tid = threadIdx.x, lane = tid & 31, wid = tid >> 5;
    const int n0 = blockIdx.x << 7, m0 = blockIdx.y << 7;
    const int wm = (wid & 1) << 6;     // 0 / 64
    const int wn = (wid >> 1) << 5;    // 0 / 32 / 64 / 96

    float acc[4][4][4];
    #pragma unroll
    for (int mi = 0; mi < 4; mi++)
        #pragma unroll
        for (int ni = 0; ni < 4; ni++)
            #pragma unroll
            for (int e = 0; e < 4; e++) acc[mi][ni][e] = 0.f;

    // per-thread load coords (512 16B chunks per matrix; 2 per thread)
    const int r0 = tid >> 2, seg0 = tid & 3;           // chunk 0
    const int r1 = (tid + 256) >> 2, seg1 = tid & 3;   // chunk 1

    const __nv_bfloat16* srcs[4] = {Ah, Al, Bh, Bl};

    auto load_stage = [&](int buf, int k0) {
        uint32_t stage = sb + (uint32_t)buf * STAGE_BYTES;
        #pragma unroll
        for (int t = 0; t < 4; t++) {
            const __nv_bfloat16* src = srcs[t];
            int base_row = (t < 2) ? m0 : n0;
            uint32_t mb = stage + t * 8192;
            cp_async16(mb + swz(r0, seg0 << 4),
                       src + (size_t)(base_row + r0) * K + k0 + seg0 * 8);
            cp_async16(mb + swz(r1, seg1 << 4),
                       src + (size_t)(base_row + r1) * K + k0 + seg1 * 8);
        }
        CP_COMMIT();
    };

    const int NCH = K >> 5;
    load_stage(0, 0);

    for (int i = 0; i < NCH; i++) {
        int buf = i & 1;
        if (i + 1 < NCH) {
            load_stage(buf ^ 1, (i + 1) << 5);
            CP_WAIT(1);
        } else {
            CP_WAIT(0);
        }
        __syncthreads();

        uint32_t stage = sb + (uint32_t)buf * STAGE_BYTES;
        #pragma unroll
        for (int ks = 0; ks < 2; ks++) {
            uint32_t a_h[4][4], a_l[4][4], b_h[4][2], b_l[4][2];
            int akb = ks * 32 + ((lane >> 4) & 1) * 16;
            int bkb = ks * 32 + ((lane >> 3) & 1) * 16;
            #pragma unroll
            for (int mi = 0; mi < 4; mi++) {
                int row = wm + mi * 16 + (lane & 15);
                uint32_t so = swz(row, akb);
                LDSM_X4(a_h[mi], stage + ST_AH + so);
                LDSM_X4(a_l[mi], stage + ST_AL + so);
            }
            #pragma unroll
            for (int ni = 0; ni < 4; ni++) {
                int row = wn + ni * 8 + (lane & 7);
                uint32_t so = swz(row, bkb);
                LDSM_X2(b_h[ni], stage + ST_BH + so);
                LDSM_X2(b_l[ni], stage + ST_BL + so);
            }
            #pragma unroll
            for (int mi = 0; mi < 4; mi++)
                #pragma unroll
                for (int ni = 0; ni < 4; ni++) {
                    MMA_BF16(acc[mi][ni], a_h[mi], b_h[ni]);
                    MMA_BF16(acc[mi][ni], a_l[mi], b_h[ni]);
                    MMA_BF16(acc[mi][ni], a_h[mi], b_l[ni]);
                }
        }
        __syncthreads();
    }

    // ---- epilogue: direct global stores (float2 pairs) ----
    const int er = m0 + wm + (lane >> 2);
    const int ec = n0 + wn + (lane & 3) * 2;
    #pragma unroll
    for (int mi = 0; mi < 4; mi++) {
        #pragma unroll
        for (int ni = 0; ni < 4; ni++) {
            float* p = C + (size_t)(er + mi * 16) * N + ec + ni * 8;
            *(float2*)p             = make_float2(acc[mi][ni][0], acc[mi][ni][1]);
            *(float2*)(p + 8 * (size_t)N) = make_float2(acc[mi][ni][2], acc[mi][ni][3]);
        }
    }
}

// ---------------- RoPE apply (in-place on q and k sections) ----------------
__global__ void rope_apply_kernel() {
    int s = blockIdx.x;
    int w = blockIdx.y;                       // 0 = q section, 1 = k section
    float* base = g_proj + (size_t)s * QKVN + w * HID;
    for (int i = threadIdx.x; i < HEADS * 64; i += blockDim.x) {
        int h = i >> 6, d = i & 63;
        float c  = g_cos[s * 64 + d];
        float sn = g_sin[s * 64 + d];
        float x1 = base[h * 128 + d];
        float x2 = base[h * 128 + d + 64];
        base[h * 128 + d]      = x1 * c - x2 * sn;
        base[h * 128 + d + 64] = x2 * c + x1 * sn;
    }
}

// ---------------- fp32 flash attention (causal) ----------------
__global__ __launch_bounds__(256)
void flash_attn_kernel(float* __restrict__ out) {
    extern __shared__ float sm[];
    float* Qs = sm;                    // [64][129]
    float* Ks = sm + 64 * 129;         // [64][129]
    float* Vs = sm + 2 * 64 * 129;     // [64][129]
    float* Ps = sm + 3 * 64 * 129;     // [64][68]
    const int qt = blockIdx.x, h = blockIdx.y;
    const int tid = threadIdx.x;
    const int tx = tid & 15, ty = tid >> 4;
    const float* qb = g_proj + (size_t)h * HDIM;
    const float* kb = g_proj + HID + (size_t)h * HDIM;
    const float* vb = g_proj + 2 * HID + (size_t)h * HDIM;
    const float scale = 0.08838834764831845f;   // 1/sqrt(128)

    for (int idx = tid; idx < 64 * 32; idx += 256) {
        int r = idx >> 5, c = (idx & 31) << 2;
        float4 v = *(const float4*)(qb + (size_t)(qt * 64 + r) * QKVN + c);
        Qs[r * 129 + c]     = v.x; Qs[r * 129 + c + 1] = v.y;
        Qs[r * 129 + c + 2] = v.z; Qs[r * 129 + c + 3] = v.w;
    }

    float m[4], l[4], Oa[4][8];
    #pragma unroll
    for (int i = 0; i < 4; i++) {
        m[i] = neg_inf(); l[i] = 0.f;
        #pragma unroll
        for (int j = 0; j < 8; j++) Oa[i][j] = 0.f;
    }

    for (int kt = 0; kt <= qt; kt++) {
        __syncthreads();
        for (int idx = tid; idx < 64 * 32; idx += 256) {
            int r = idx >> 5, c = (idx & 31) << 2;
            float4 kv = *(const float4*)(kb + (size_t)(kt * 64 + r) * QKVN + c);
            Ks[r * 129 + c]     = kv.x; Ks[r * 129 + c + 1] = kv.y;
            Ks[r * 129 + c + 2] = kv.z; Ks[r * 129 + c + 3] = kv.w;
            float4 vv = *(const float4*)(vb + (size_t)(kt * 64 + r) * QKVN + c);
            Vs[r * 129 + c]     = vv.x; Vs[r * 129 + c + 1] = vv.y;
            Vs[r * 129 + c + 2] = vv.z; Vs[r * 129 + c + 3] = vv.w;
        }
        __syncthreads();

        float s4[4][4];
        #pragma unroll
        for (int i = 0; i < 4; i++)
            #pragma unroll
            for (int j = 0; j < 4; j++) s4[i][j] = 0.f;
        #pragma unroll 8
        for (int d = 0; d < 128; d++) {
            float q0 = Qs[(ty * 4 + 0) * 129 + d];
            float q1 = Qs[(ty * 4 + 1) * 129 + d];
            float q2 = Qs[(ty * 4 + 2) * 129 + d];
            float q3 = Qs[(ty * 4 + 3) * 129 + d];
            float k0 = Ks[(tx +  0) * 129 + d];
            float k1 = Ks[(tx + 16) * 129 + d];
            float k2 = Ks[(tx + 32) * 129 + d];
            float k3 = Ks[(tx + 48) * 129 + d];
            s4[0][0] += q0 * k0; s4[0][1] += q0 * k1; s4[0][2] += q0 * k2; s4[0][3] += q0 * k3;
            s4[1][0] += q1 * k0; s4[1][1] += q1 * k1; s4[1][2] += q1 * k2; s4[1][3] += q1 * k3;
            s4[2][0] += q2 * k0; s4[2][1] += q2 * k1; s4[2][2] += q2 * k2; s4[2][3] += q2 * k3;
            s4[3][0] += q3 * k0; s4[3][1] += q3 * k1; s4[3][2] += q3 * k2; s4[3][3] += q3 * k3;
        }

        #pragma unroll
        for (int i = 0; i < 4; i++) {
            int row = qt * 64 + ty * 4 + i;
            float tm = neg_inf();
            #pragma unroll
            for (int j = 0; j < 4; j++) {
                int col = kt * 64 + tx + 16 * j;
                float v = (col <= row) ? s4[i][j] * scale : neg_inf();
                s4[i][j] = v;
                tm = fmaxf(tm, v);
            }
            #pragma unroll
            for (int o = 8; o; o >>= 1)
                tm = fmaxf(tm, __shfl_xor_sync(0xffffffffu, tm, o));
            float mn = fmaxf(m[i], tm);
            float alpha = __expf(m[i] - mn);
            float rs = 0.f;
            #pragma unroll
            for (int j = 0; j < 4; j++) {
                float p = __expf(s4[i][j] - mn);
                rs += p;
                Ps[(ty * 4 + i) * 68 + tx + 16 * j] = p;
            }
            #pragma unroll
            for (int o = 8; o; o >>= 1)
                rs += __shfl_xor_sync(0xffffffffu, rs, o);
            l[i] = l[i] * alpha + rs;
            m[i] = mn;
            #pragma unroll
            for (int j = 0; j < 8; j++) Oa[i][j] *= alpha;
        }
        __syncthreads();

        #pragma unroll 4
        for (int c = 0; c < 64; c++) {
            float p0 = Ps[(ty * 4 + 0) * 68 + c];
            float p1 = Ps[(ty * 4 + 1) * 68 + c];
            float p2 = Ps[(ty * 4 + 2) * 68 + c];
            float p3 = Ps[(ty * 4 + 3) * 68 + c];
            #pragma unroll
            for (int j = 0; j < 8; j++) {
                float v = Vs[c * 129 + tx + 16 * j];
                Oa[0][j] += p0 * v;
                Oa[1][j] += p1 * v;
                Oa[2][j] += p2 * v;
                Oa[3][j] += p3 * v;
            }
        }
    }

    #pragma unroll
    for (int i = 0; i < 4; i++) {
        float inv = 1.f / l[i];
        int row = qt * 64 + ty * 4 + i;
        #pragma unroll
        for (int j = 0; j < 8; j++)
            out[(size_t)row * HID + h * HDIM + tx + 16 * j] = Oa[i][j] * inv;
    }
}

extern "C" void kernel_launch(void* const* d_in, const int* in_sizes, int n_in,
                              void* d_out, int out_size) {
    const float* hidden = (const float*)d_in[0];
    const int*   pos    = (const int*)d_in[1];
    const int*   qkv_qw = (const int*)d_in[2];
    const float* qkv_s  = (const float*)d_in[3];
    const float* qkv_z  = (const float*)d_in[4];
    const int*   o_qw   = (const int*)d_in[5];
    const float* o_s    = (const float*)d_in[6];
    const float* o_z    = (const float*)d_in[7];
    float* out = (float*)d_out;

    void* p;
    cudaGetSymbolAddress(&p, g_proj); float* proj = (float*)p;
    cudaGetSymbolAddress(&p, g_attn); float* attn = (float*)p;
    cudaGetSymbolAddress(&p, g_ah);   __nv_bfloat16* ah = (__nv_bfloat16*)p;
    cudaGetSymbolAddress(&p, g_al);   __nv_bfloat16* al = (__nv_bfloat16*)p;
    cudaGetSymbolAddress(&p, g_bh);   __nv_bfloat16* bh = (__nv_bfloat16*)p;
    cudaGetSymbolAddress(&p, g_bl);   __nv_bfloat16* bl = (__nv_bfloat16*)p;

    int gemm_smem = 2 * STAGE_BYTES;                               // 65536
    cudaFuncSetAttribute(gemm_mma_kernel,
                         cudaFuncAttributeMaxDynamicSharedMemorySize, gemm_smem);
    int fa_smem = (3 * 64 * 129 + 64 * 68) * (int)sizeof(float);   // 116480
    cudaFuncSetAttribute(flash_attn_kernel,
                         cudaFuncAttributeMaxDynamicSharedMemorySize, fa_smem);

    // 1. RoPE tables
    rope_tables_kernel<<<SEQ, 64>>>(pos);

    // 2. split activations; dequant+transpose QKV weights
    split_kernel<<<(SEQ * HID) / (256 * 4), 256>>>(hidden, ah, al);
    dequant_transpose_kernel<<<dim3(QKVN / 32, HID / 32), 256>>>(
        qkv_qw, qkv_s, qkv_z, bh, bl, HID, QKVN);

    // 3. QKV projection (bf16x3 mma.sync GEMM)
    gemm_mma_kernel<<<dim3(QKVN / 128, SEQ / 128), 256, gemm_smem>>>(
        ah, al, bh, bl, proj, SEQ, QKVN, HID);

    // 4. RoPE on q and k
    rope_apply_kernel<<<dim3(SEQ, 2), 256>>>();

    // 5. causal flash attention
    flash_attn_kernel<<<dim3(SEQ / 64, HEADS), 256, fa_smem>>>(attn);

    // 6. split attention output; dequant+transpose O weights (reuse bh/bl)
    split_kernel<<<(SEQ * HID) / (256 * 4), 256>>>(attn, ah, al);
    dequant_transpose_kernel<<<dim3(HID / 32, HID / 32), 256>>>(
        o_qw, o_s, o_z, bh, bl, HID, HID);

    // 7. output projection
    gemm_mma_kernel<<<dim3(HID / 128, SEQ / 128), 256, gemm_smem>>>(
        ah, al, bh, bl, out, SEQ, HID, HID);
}

// round 5
// speedup vs baseline: 2.6955x; 1.4237x over previous
#include <cuda_runtime.h>
#include <cuda_bf16.h>
#include <math.h>
#include <stdint.h>

#define SEQ   2048
#define HID   4096
#define HEADS 32
#define HDIM  128
#define QKVN  12288

// ---------------- scratch (device globals; no runtime allocation) ----------------
__device__ float g_proj[(size_t)SEQ * QKVN];                 // qkv projection [s, 3*HID]
__device__ float g_attn[(size_t)SEQ * HID];                  // attention output [s, HID]
__device__ float g_cos[SEQ * 64];
__device__ float g_sin[SEQ * 64];
__device__ __nv_bfloat16 g_ah[(size_t)SEQ * HID];            // activation hi
__device__ __nv_bfloat16 g_al[(size_t)SEQ * HID];            // activation lo
__device__ __nv_bfloat16 g_bh[(size_t)QKVN * HID];           // weight^T hi [N,K]
__device__ __nv_bfloat16 g_bl[(size_t)QKVN * HID];           // weight^T lo [N,K]
__device__ __nv_bfloat16 g_qh[(size_t)HEADS * SEQ * HDIM];   // Q hi  [h][s][d] (scale folded)
__device__ __nv_bfloat16 g_ql[(size_t)HEADS * SEQ * HDIM];
__device__ __nv_bfloat16 g_kh[(size_t)HEADS * SEQ * HDIM];   // K hi  [h][s][d]
__device__ __nv_bfloat16 g_kl[(size_t)HEADS * SEQ * HDIM];
__device__ __nv_bfloat16 g_vth[(size_t)HEADS * HDIM * SEQ];  // V^T hi [h][d][s]
__device__ __nv_bfloat16 g_vtl[(size_t)HEADS * HDIM * SEQ];

__device__ __forceinline__ float neg_inf() { return __int_as_float(0xff800000); }

__device__ __forceinline__ uint32_t smem_to_u32(const void* p) {
    uint32_t a;
    asm("{ .reg .u64 t; cvta.to.shared.u64 t, %1; cvt.u32.u64 %0, t; }" : "=r"(a) : "l"(p));
    return a;
}
__device__ __forceinline__ void cp_async16(uint32_t dst, const void* src) {
    asm volatile("cp.async.cg.shared.global [%0], [%1], 16;" :: "r"(dst), "l"(src));
}
#define CP_COMMIT() asm volatile("cp.async.commit_group;" ::: "memory")
#define CP_WAIT(n)  asm volatile("cp.async.wait_group %0;" :: "n"(n) : "memory")

#define LDSM_X4(r, a) \
    asm volatile("ldmatrix.sync.aligned.m8n8.x4.shared.b16 {%0,%1,%2,%3}, [%4];" \
        : "=r"((r)[0]), "=r"((r)[1]), "=r"((r)[2]), "=r"((r)[3]) : "r"(a))
#define LDSM_X2(r, a) \
    asm volatile("ldmatrix.sync.aligned.m8n8.x2.shared.b16 {%0,%1}, [%2];" \
        : "=r"((r)[0]), "=r"((r)[1]) : "r"(a))
#define MMA_BF16(d, a, b) \
    asm volatile("mma.sync.aligned.m16n8k16.row.col.f32.bf16.bf16.f32 " \
        "{%0,%1,%2,%3}, {%4,%5,%6,%7}, {%8,%9}, {%0,%1,%2,%3};" \
        : "+f"((d)[0]), "+f"((d)[1]), "+f"((d)[2]), "+f"((d)[3]) \
        : "r"((a)[0]), "r"((a)[1]), "r"((a)[2]), "r"((a)[3]), "r"((b)[0]), "r"((b)[1]))

// GEMM smem tile: 128 rows x 64B, XOR swizzle (validated R4)
__device__ __forceinline__ uint32_t swz(int r, int kbyte) {
    uint32_t seg = ((uint32_t)(kbyte >> 4)) ^ (((uint32_t)r >> 1) & 3u);
    return (uint32_t)r * 64u + (seg << 4) + (uint32_t)(kbyte & 15);
}

// ---------------- RoPE tables ----------------
__global__ void rope_tables_kernel(const int* __restrict__ pos_ids) {
    int s = blockIdx.x;
    int d = threadIdx.x;
    double inv = pow(10000.0, -(double)(2 * d) / 128.0);
    double ang = (double)pos_ids[s] * inv;
    g_cos[s * 64 + d] = (float)cos(ang);
    g_sin[s * 64 + d] = (float)sin(ang);
}

// ---------------- fp32 -> bf16 hi/lo split ----------------
__global__ __launch_bounds__(256)
void split_kernel(const float* __restrict__ X, __nv_bfloat16* __restrict__ H,
                  __nv_bfloat16* __restrict__ L) {
    int i = (blockIdx.x * 256 + threadIdx.x) * 4;
    float4 v = *(const float4*)(X + i);
    __nv_bfloat16 h0 = __float2bfloat16(v.x), h1 = __float2bfloat16(v.y);
    __nv_bfloat16 h2 = __float2bfloat16(v.z), h3 = __float2bfloat16(v.w);
    H[i + 0] = h0; H[i + 1] = h1; H[i + 2] = h2; H[i + 3] = h3;
    L[i + 0] = __float2bfloat16(v.x - __bfloat162float(h0));
    L[i + 1] = __float2bfloat16(v.y - __bfloat162float(h1));
    L[i + 2] = __float2bfloat16(v.z - __bfloat162float(h2));
    L[i + 3] = __float2bfloat16(v.w - __bfloat162float(h3));
}

// ---------------- dequant + transpose: W[k,n] -> B[n,k] bf16 hi/lo ----------------
__global__ __launch_bounds__(256)
void dequant_transpose_kernel(const int* __restrict__ Qw, const float* __restrict__ Sc,
                              const float* __restrict__ Zr, __nv_bfloat16* __restrict__ Bh,
                              __nv_bfloat16* __restrict__ Bl, int K, int N) {
    __shared__ float w[32][33];
    int n0 = blockIdx.x * 32, k0 = blockIdx.y * 32;
    int tx = threadIdx.x & 31, ty = threadIdx.x >> 5;
    int g = k0 >> 7;
    float s = Sc[(size_t)g * N + n0 + tx];
    float z = Zr[(size_t)g * N + n0 + tx];
    #pragma unroll
    for (int rr = 0; rr < 32; rr += 8) {
        int q = Qw[(size_t)(k0 + rr + ty) * N + n0 + tx];
        w[rr + ty][tx] = ((float)q - z) * s;
    }
    __syncthreads();
    #pragma unroll
    for (int rr = 0; rr < 32; rr += 8) {
        int n = rr + ty;
        float v = w[tx][n];
        __nv_bfloat16 h = __float2bfloat16(v);
        size_t o = (size_t)(n0 + n) * K + k0 + tx;
        Bh[o] = h;
        Bl[o] = __float2bfloat16(v - __bfloat162float(h));
    }
}

// ---------------- bf16x3 mma.sync GEMM (validated R4) ----------------
#define ST_AH 0
#define ST_AL 8192
#define ST_BH 16384
#define ST_BL 24576
#define STAGE_BYTES 32768

__global__ __launch_bounds__(256, 1)
void gemm_mma_kernel(const __nv_bfloat16* __restrict__ Ah,
                     const __nv_bfloat16* __restrict__ Al,
                     const __nv_bfloat16* __restrict__ Bh,
                     const __nv_bfloat16* __restrict__ Bl,
                     float* __restrict__ C, int M, int N, int K) {
    extern __shared__ char smraw[];
    const uint32_t sb = smem_to_u32(smraw);
    const int tid = threadIdx.x, lane = tid & 31, wid = tid >> 5;
    const int n0 = blockIdx.x << 7, m0 = blockIdx.y << 7;
    const int wm = (wid & 1) << 6;
    const int wn = (wid >> 1) << 5;

    float acc[4][4][4];
    #pragma unroll
    for (int mi = 0; mi < 4; mi++)
        #pragma unroll
        for (int ni = 0; ni < 4; ni++)
            #pragma unroll
            for (int e = 0; e < 4; e++) acc[mi][ni][e] = 0.f;

    const int r0 = tid >> 2, seg0 = tid & 3;
    const int r1 = (tid + 256) >> 2, seg1 = tid & 3;
    const __nv_bfloat16* srcs[4] = {Ah, Al, Bh, Bl};

    auto load_stage = [&](int buf, int k0) {
        uint32_t stage = sb + (uint32_t)buf * STAGE_BYTES;
        #pragma unroll
        for (int t = 0; t < 4; t++) {
            const __nv_bfloat16* src = srcs[t];
            int base_row = (t < 2) ? m0 : n0;
            uint32_t mb = stage + t * 8192;
            cp_async16(mb + swz(r0, seg0 << 4),
                       src + (size_t)(base_row + r0) * K + k0 + seg0 * 8);
            cp_async16(mb + swz(r1, seg1 << 4),
                       src + (size_t)(base_row + r1) * K + k0 + seg1 * 8);
        }
        CP_COMMIT();
    };

    const int NCH = K >> 5;
    load_stage(0, 0);

    for (int i = 0; i < NCH; i++) {
        int buf = i & 1;
        if (i + 1 < NCH) {
            load_stage(buf ^ 1, (i + 1) << 5);
            CP_WAIT(1);
        } else {
            CP_WAIT(0);
        }
        __syncthreads();

        uint32_t stage = sb + (uint32_t)buf * STAGE_BYTES;
        #pragma unroll
        for (int ks = 0; ks < 2; ks++) {
            uint32_t a_h[4][4], a_l[4][4], b_h[4][2], b_l[4][2];
            int akb = ks * 32 + ((lane >> 4) & 1) * 16;
            int bkb = ks * 32 + ((lane >> 3) & 1) * 16;
            #pragma unroll
            for (int mi = 0; mi < 4; mi++) {
                int row = wm + mi * 16 + (lane & 15);
                uint32_t so = swz(row, akb);
                LDSM_X4(a_h[mi], stage + ST_AH + so);
                LDSM_X4(a_l[mi], stage + ST_AL + so);
            }
            #pragma unroll
            for (int ni = 0; ni < 4; ni++) {
                int row = wn + ni * 8 + (lane & 7);
                uint32_t so = swz(row, bkb);
                LDSM_X2(b_h[ni], stage + ST_BH + so);
                LDSM_X2(b_l[ni], stage + ST_BL + so);
            }
            #pragma unroll
            for (int mi = 0; mi < 4; mi++)
                #pragma unroll
                for (int ni = 0; ni < 4; ni++) {
                    MMA_BF16(acc[mi][ni], a_h[mi], b_h[ni]);
                    MMA_BF16(acc[mi][ni], a_l[mi], b_h[ni]);
                    MMA_BF16(acc[mi][ni], a_h[mi], b_l[ni]);
                }
        }
        __syncthreads();
    }

    const int er = m0 + wm + (lane >> 2);
    const int ec = n0 + wn + (lane & 3) * 2;
    #pragma unroll
    for (int mi = 0; mi < 4; mi++) {
        #pragma unroll
        for (int ni = 0; ni < 4; ni++) {
            float* p = C + (size_t)(er + mi * 16) * N + ec + ni * 8;
            *(float2*)p                   = make_float2(acc[mi][ni][0], acc[mi][ni][1]);
            *(float2*)(p + 8 * (size_t)N) = make_float2(acc[mi][ni][2], acc[mi][ni][3]);
        }
    }
}

// ---------------- RoPE + split Q/K -> bf16 hi/lo [h][s][d] (scale folded into Q) ------
__global__ __launch_bounds__(256)
void rope_split_kernel() {
    int s = blockIdx.x;
    const float* row = g_proj + (size_t)s * QKVN;
    for (int it = threadIdx.x; it < 4096; it += 256) {
        int qk = it >> 11;                 // 0=q, 1=k
        int hh = (it >> 6) & 31;
        int d  = it & 63;
        float c = g_cos[s * 64 + d], sn = g_sin[s * 64 + d];
        const float* p = row + qk * HID + hh * 128;
        float x1 = p[d], x2 = p[d + 64];
        float y1 = x1 * c - x2 * sn;
        float y2 = x2 * c + x1 * sn;
        if (qk == 0) { y1 *= 0.08838834764831845f; y2 *= 0.08838834764831845f; }
        __nv_bfloat16* H = qk ? g_kh : g_qh;
        __nv_bfloat16* L = qk ? g_kl : g_ql;
        size_t o = ((size_t)hh * SEQ + s) * 128 + d;
        __nv_bfloat16 h1 = __float2bfloat16(y1), h2 = __float2bfloat16(y2);
        H[o] = h1; H[o + 64] = h2;
        L[o]      = __float2bfloat16(y1 - __bfloat162float(h1));
        L[o + 64] = __float2bfloat16(y2 - __bfloat162float(h2));
    }
}

// ---------------- V transpose + split: [s][h*128+d] -> [h][d][s] bf16 hi/lo ------------
__global__ void v_transpose_split_kernel() {
    __shared__ float t[32][33];
    int s0 = blockIdx.x * 32, d0 = blockIdx.y * 32, h = blockIdx.z;
    int tx = threadIdx.x, ty = threadIdx.y;       // 32 x 8
    #pragma unroll
    for (int rr = 0; rr < 32; rr += 8)
        t[rr + ty][tx] = g_proj[(size_t)(s0 + rr + ty) * QKVN + 2 * HID + h * 128 + d0 + tx];
    __syncthreads();
    #pragma unroll
    for (int rr = 0; rr < 32; rr += 8) {
        int d = d0 + rr + ty;
        float v = t[tx][rr + ty];
        __nv_bfloat16 hi = __float2bfloat16(v);
        size_t o = ((size_t)h * 128 + d) * SEQ + s0 + tx;
        g_vth[o] = hi;
        g_vtl[o] = __float2bfloat16(v - __bfloat162float(hi));
    }
}

// ---------------- bf16x3 mma.sync flash attention (causal) ----------------
// CTA = (head, 64 q-rows), 4 warps, warp = 16 q rows. Padded-pitch smem, no swizzle.
#define QPITCH 272                    // 128 bf16 + 8 pad (16r mod 128 distinct)
#define VPITCH 144                    // 64 bf16 + 8 pad
#define AT_QH  0
#define AT_QL  17408
#define AT_K0  34816
#define KV_KH  0
#define KV_KL  17408
#define KV_VH  34816
#define KV_VL  53248
#define AT_STAGE 71680                // KH+KL+VH+VL
#define AT_SMEM  (AT_K0 + 2 * AT_STAGE)   // 178176

__global__ __launch_bounds__(128, 1)
void attn_mma_kernel(float* __restrict__ out) {
    extern __shared__ char smraw[];
    const uint32_t sb = smem_to_u32(smraw);
    const int h  = blockIdx.x;
    const int qt = (int)gridDim.y - 1 - (int)blockIdx.y;   // big tiles first
    const int tid = threadIdx.x, lane = tid & 31, warp = tid >> 5;
    const int wm16 = warp << 4;

    const __nv_bfloat16* qhp = g_qh + ((size_t)h * SEQ + qt * 64) * 128;
    const __nv_bfloat16* qlp = g_ql + ((size_t)h * SEQ + qt * 64) * 128;
    const __nv_bfloat16* kh0 = g_kh + (size_t)h * SEQ * 128;
    const __nv_bfloat16* kl0 = g_kl + (size_t)h * SEQ * 128;
    const __nv_bfloat16* vh0 = g_vth + (size_t)h * 128 * SEQ;
    const __nv_bfloat16* vl0 = g_vtl + (size_t)h * 128 * SEQ;

    auto load_kv = [&](int kt_, int buf_) {
        uint32_t base = sb + AT_K0 + (uint32_t)buf_ * AT_STAGE;
        const __nv_bfloat16* kh = kh0 + (size_t)kt_ * 64 * 128;
        const __nv_bfloat16* kl = kl0 + (size_t)kt_ * 64 * 128;
        #pragma unroll
        for (int u = 0; u < 16; u++) {
            int i = tid + u * 128;
            int m = i >> 10, c = i & 1023, r = c >> 4, seg = c & 15;
            cp_async16(base + m * 17408 + r * QPITCH + seg * 16,
                       (m ? kl : kh) + r * 128 + seg * 8);
        }
        const __nv_bfloat16* vh = vh0 + kt_ * 64;
        const __nv_bfloat16* vl = vl0 + kt_ * 64;
        #pragma unroll
        for (int u = 0; u < 16; u++) {
            int i = tid + u * 128;
            int m = i >> 10, c = i & 1023, r = c >> 3, seg = c & 7;
            cp_async16(base + KV_VH + m * 18432 + r * VPITCH + seg * 16,
                       (m ? vl : vh) + (size_t)r * SEQ + seg * 8);
        }
    };

    // Q tiles (hi + lo) + first KV tile in group 0
    #pragma unroll
    for (int u = 0; u < 16; u++) {
        int i = tid + u * 128;
        int m = i >> 10, c = i & 1023, r = c >> 4, seg = c & 15;
        const __nv_bfloat16* src = m ? qlp : qhp;
        cp_async16(sb + (m ? AT_QL : AT_QH) + r * QPITCH + seg * 16,
                   src + r * 128 + seg * 8);
    }
    load_kv(0, 0);
    CP_COMMIT();

    float o[16][4];
    #pragma unroll
    for (int n = 0; n < 16; n++)
        #pragma unroll
        for (int e = 0; e < 4; e++) o[n][e] = 0.f;
    float m0 = neg_inf(), m1 = neg_inf(), l0 = 0.f, l1 = 0.f;

    for (int kt = 0; kt <= qt; kt++) {
        int buf = kt & 1;
        if (kt < qt) {
            load_kv(kt + 1, buf ^ 1);
            CP_COMMIT();
            CP_WAIT(1);
        } else {
            CP_WAIT(0);
        }
        __syncthreads();

        uint32_t kvb = sb + AT_K0 + (uint32_t)buf * AT_STAGE;

        // ---- S = Qh Kh + Ql Kh + Qh Kl ----
        float s4[8][4];
        #pragma unroll
        for (int j = 0; j < 8; j++)
            #pragma unroll
            for (int e = 0; e < 4; e++) s4[j][e] = 0.f;
        #pragma unroll
        for (int ks = 0; ks < 8; ks++) {
            uint32_t ah[4], al[4];
            uint32_t qa = (uint32_t)(wm16 + (lane & 15)) * QPITCH
                        + ks * 32 + ((lane >> 4) & 1) * 16;
            LDSM_X4(ah, sb + AT_QH + qa);
            LDSM_X4(al, sb + AT_QL + qa);
            #pragma unroll
            for (int j = 0; j < 8; j++) {
                uint32_t bh[2], bl[2];
                uint32_t ka = (uint32_t)(j * 8 + (lane & 7)) * QPITCH
                            + ks * 32 + ((lane >> 3) & 1) * 16;
                LDSM_X2(bh, kvb + KV_KH + ka);
                LDSM_X2(bl, kvb + KV_KL + ka);
                MMA_BF16(s4[j], ah, bh);
                MMA_BF16(s4[j], al, bh);
                MMA_BF16(s4[j], ah, bl);
            }
        }

        // ---- causal mask (diagonal tile only; scale already folded into Q) ----
        if (kt == qt) {
            int colb = 2 * (lane & 3);
            int rowb = wm16 + (lane >> 2);
            #pragma unroll
            for (int j = 0; j < 8; j++) {
                int c0 = j * 8 + colb;
                if (c0     > rowb)     s4[j][0] = neg_inf();
                if (c0 + 1 > rowb)     s4[j][1] = neg_inf();
                if (c0     > rowb + 8) s4[j][2] = neg_inf();
                if (c0 + 1 > rowb + 8) s4[j][3] = neg_inf();
            }
        }

        // ---- online softmax ----
        float tm0 = neg_inf(), tm1 = neg_inf();
        #pragma unroll
        for (int j = 0; j < 8; j++) {
            tm0 = fmaxf(tm0, fmaxf(s4[j][0], s4[j][1]));
            tm1 = fmaxf(tm1, fmaxf(s4[j][2], s4[j][3]));
        }
        tm0 = fmaxf(tm0, __shfl_xor_sync(0xffffffffu, tm0, 1));
        tm0 = fmaxf(tm0, __shfl_xor_sync(0xffffffffu, tm0, 2));
        tm1 = fmaxf(tm1, __shfl_xor_sync(0xffffffffu, tm1, 1));
        tm1 = fmaxf(tm1, __shfl_xor_sync(0xffffffffu, tm1, 2));
        float mn0 = fmaxf(m0, tm0), mn1 = fmaxf(m1, tm1);
        float a0 = __expf(m0 - mn0), a1 = __expf(m1 - mn1);
        m0 = mn0; m1 = mn1;

        float rs0 = 0.f, rs1 = 0.f;
        uint32_t pah[4][4], pal[4][4];
        #pragma unroll
        for (int j = 0; j < 8; j++) {
            float p0 = __expf(s4[j][0] - mn0), p1 = __expf(s4[j][1] - mn0);
            float p2 = __expf(s4[j][2] - mn1), p3 = __expf(s4[j][3] - mn1);
            rs0 += p0 + p1; rs1 += p2 + p3;
            __nv_bfloat16 b0 = __float2bfloat16(p0), b1 = __float2bfloat16(p1);
            __nv_bfloat16 b2 = __float2bfloat16(p2), b3 = __float2bfloat16(p3);
            uint32_t h01 = ((uint32_t)__bfloat16_as_ushort(b1) << 16) | __bfloat16_as_ushort(b0);
            uint32_t h23 = ((uint32_t)__bfloat16_as_ushort(b3) << 16) | __bfloat16_as_ushort(b2);
            __nv_bfloat16 c0 = __float2bfloat16(p0 - __bfloat162float(b0));
            __nv_bfloat16 c1 = __float2bfloat16(p1 - __bfloat162float(b1));
            __nv_bfloat16 c2 = __float2bfloat16(p2 - __bfloat162float(b2));
            __nv_bfloat16 c3 = __float2bfloat16(p3 - __bfloat162float(b3));
            uint32_t l01 = ((uint32_t)__bfloat16_as_ushort(c1) << 16) | __bfloat16_as_ushort(c0);
            uint32_t l23 = ((uint32_t)__bfloat16_as_ushort(c3) << 16) | __bfloat16_as_ushort(c2);
            int k2 = j >> 1, odd = (j & 1) << 1;
            pah[k2][odd] = h01; pah[k2][odd + 1] = h23;
            pal[k2][odd] = l01; pal[k2][odd + 1] = l23;
        }
        rs0 += __shfl_xor_sync(0xffffffffu, rs0, 1);
        rs0 += __shfl_xor_sync(0xffffffffu, rs0, 2);
        rs1 += __shfl_xor_sync(0xffffffffu, rs1, 1);
        rs1 += __shfl_xor_sync(0xffffffffu, rs1, 2);
        l0 = l0 * a0 + rs0;
        l1 = l1 * a1 + rs1;
        #pragma unroll
        for (int n = 0; n < 16; n++) {
            o[n][0] *= a0; o[n][1] *= a0; o[n][2] *= a1; o[n][3] *= a1;
        }

        // ---- O += Ph Vh + Pl Vh + Ph Vl ----
        #pragma unroll
        for (int ks2 = 0; ks2 < 4; ks2++) {
            #pragma unroll
            for (int n = 0; n < 16; n++) {
                uint32_t vh[2], vl[2];
                uint32_t va = (uint32_t)(n * 8 + (lane & 7)) * VPITCH
                            + ks2 * 32 + ((lane >> 3) & 1) * 16;
                LDSM_X2(vh, kvb + KV_VH + va);
                LDSM_X2(vl, kvb + KV_VL + va);
                MMA_BF16(o[n], pah[ks2], vh);
                MMA_BF16(o[n], pal[ks2], vh);
                MMA_BF16(o[n], pah[ks2], vl);
            }
        }
        __syncthreads();
    }

    // ---- epilogue ----
    float inv0 = 1.f / l0, inv1 = 1.f / l1;
    int rg = qt * 64 + wm16 + (lane >> 2);
    int cb = h * 128 + 2 * (lane & 3);
    #pragma unroll
    for (int n = 0; n < 16; n++) {
        float* p0 = out + (size_t)rg * HID + cb + n * 8;
        *(float2*)p0 = make_float2(o[n][0] * inv0, o[n][1] * inv0);
        float* p1 = out + (size_t)(rg + 8) * HID + cb + n * 8;
        *(float2*)p1 = make_float2(o[n][2] * inv1, o[n][3] * inv1);
    }
}

extern "C" void kernel_launch(void* const* d_in, const int* in_sizes, int n_in,
                              void* d_out, int out_size) {
    const float* hidden = (const float*)d_in[0];
    const int*   pos    = (const int*)d_in[1];
    const int*   qkv_qw = (const int*)d_in[2];
    const float* qkv_s  = (const float*)d_in[3];
    const float* qkv_z  = (const float*)d_in[4];
    const int*   o_qw   = (const int*)d_in[5];
    const float* o_s    = (const float*)d_in[6];
    const float* o_z    = (const float*)d_in[7];
    float* out = (float*)d_out;

    void* p;
    cudaGetSymbolAddress(&p, g_proj); float* proj = (float*)p;
    cudaGetSymbolAddress(&p, g_attn); float* attn = (float*)p;
    cudaGetSymbolAddress(&p, g_ah);   __nv_bfloat16* ah = (__nv_bfloat16*)p;
    cudaGetSymbolAddress(&p, g_al);   __nv_bfloat16* al = (__nv_bfloat16*)p;
    cudaGetSymbolAddress(&p, g_bh);   __nv_bfloat16* bh = (__nv_bfloat16*)p;
    cudaGetSymbolAddress(&p, g_bl);   __nv_bfloat16* bl = (__nv_bfloat16*)p;

    int gemm_smem = 2 * STAGE_BYTES;
    cudaFuncSetAttribute(gemm_mma_kernel,
                         cudaFuncAttributeMaxDynamicSharedMemorySize, gemm_smem);
    cudaFuncSetAttribute(attn_mma_kernel,
                         cudaFuncAttributeMaxDynamicSharedMemorySize, AT_SMEM);

    // 1. RoPE tables
    rope_tables_kernel<<<SEQ, 64>>>(pos);

    // 2. split activations; dequant+transpose QKV weights
    split_kernel<<<(SEQ * HID) / (256 * 4), 256>>>(hidden, ah, al);
    dequant_transpose_kernel<<<dim3(QKVN / 32, HID / 32), 256>>>(
        qkv_qw, qkv_s, qkv_z, bh, bl, HID, QKVN);

    // 3. QKV projection
    gemm_mma_kernel<<<dim3(QKVN / 128, SEQ / 128), 256, gemm_smem>>>(
        ah, al, bh, bl, proj, SEQ, QKVN, HID);

    // 4. RoPE + split Q/K; transpose + split V
    rope_split_kernel<<<SEQ, 256>>>();
    v_transpose_split_kernel<<<dim3(SEQ / 32, HDIM / 32, HEADS), dim3(32, 8)>>>();

    // 5. causal flash attention on tensor cores
    attn_mma_kernel<<<dim3(HEADS, SEQ / 64), 128, AT_SMEM>>>(attn);

    // 6. split attention output; dequant+transpose O weights
    split_kernel<<<(SEQ * HID) / (256 * 4), 256>>>(attn, ah, al);
    dequant_transpose_kernel<<<dim3(HID / 32, HID / 32), 256>>>(
        o_qw, o_s, o_z, bh, bl, HID, HID);

    // 7. output projection
    gemm_mma_kernel<<<dim3(HID / 128, SEQ / 128), 256, gemm_smem>>>(
        ah, al, bh, bl, out, SEQ, HID, HID);
}

// round 6
// speedup vs baseline: 2.8309x; 1.0502x over previous
#include <cuda_runtime.h>
#include <cuda_bf16.h>
#include <math.h>
#include <stdint.h>

#define SEQ   2048
#define HID   4096
#define HEADS 32
#define HDIM  128
#define QKVN  12288

// ---------------- scratch (device globals; no runtime allocation) ----------------
__device__ float g_proj[(size_t)SEQ * QKVN];                 // qkv projection [s, 3*HID]
__device__ float g_attn[(size_t)SEQ * HID];                  // attention output [s, HID]
__device__ float g_cos[SEQ * 64];
__device__ float g_sin[SEQ * 64];
__device__ __nv_bfloat16 g_ah[(size_t)SEQ * HID];            // activation hi
__device__ __nv_bfloat16 g_al[(size_t)SEQ * HID];            // activation lo
__device__ __nv_bfloat16 g_bh[(size_t)QKVN * HID];           // weight^T hi [N,K]
__device__ __nv_bfloat16 g_bl[(size_t)QKVN * HID];           // weight^T lo [N,K]
__device__ __nv_bfloat16 g_qh[(size_t)HEADS * SEQ * HDIM];   // Q hi  [h][s][d] (scale folded)
__device__ __nv_bfloat16 g_ql[(size_t)HEADS * SEQ * HDIM];
__device__ __nv_bfloat16 g_kh[(size_t)HEADS * SEQ * HDIM];   // K hi  [h][s][d]
__device__ __nv_bfloat16 g_kl[(size_t)HEADS * SEQ * HDIM];
__device__ __nv_bfloat16 g_vth[(size_t)HEADS * HDIM * SEQ];  // V^T hi [h][d][s]
__device__ __nv_bfloat16 g_vtl[(size_t)HEADS * HDIM * SEQ];

__device__ __forceinline__ float neg_inf() { return __int_as_float(0xff800000); }

__device__ __forceinline__ uint32_t smem_to_u32(const void* p) {
    uint32_t a;
    asm("{ .reg .u64 t; cvta.to.shared.u64 t, %1; cvt.u32.u64 %0, t; }" : "=r"(a) : "l"(p));
    return a;
}
__device__ __forceinline__ void cp_async16(uint32_t dst, const void* src) {
    asm volatile("cp.async.cg.shared.global [%0], [%1], 16;" :: "r"(dst), "l"(src));
}
#define CP_COMMIT() asm volatile("cp.async.commit_group;" ::: "memory")
#define CP_WAIT(n)  asm volatile("cp.async.wait_group %0;" :: "n"(n) : "memory")

#define LDSM_X4(r, a) \
    asm volatile("ldmatrix.sync.aligned.m8n8.x4.shared.b16 {%0,%1,%2,%3}, [%4];" \
        : "=r"((r)[0]), "=r"((r)[1]), "=r"((r)[2]), "=r"((r)[3]) : "r"(a))
#define LDSM_X2(r, a) \
    asm volatile("ldmatrix.sync.aligned.m8n8.x2.shared.b16 {%0,%1}, [%2];" \
        : "=r"((r)[0]), "=r"((r)[1]) : "r"(a))
#define MMA_BF16(d, a, b) \
    asm volatile("mma.sync.aligned.m16n8k16.row.col.f32.bf16.bf16.f32 " \
        "{%0,%1,%2,%3}, {%4,%5,%6,%7}, {%8,%9}, {%0,%1,%2,%3};" \
        : "+f"((d)[0]), "+f"((d)[1]), "+f"((d)[2]), "+f"((d)[3]) \
        : "r"((a)[0]), "r"((a)[1]), "r"((a)[2]), "r"((a)[3]), "r"((b)[0]), "r"((b)[1]))

// smem tile rows are 64B wide; 16B-segment XOR swizzle (validated R4/R5)
__device__ __forceinline__ uint32_t swz(int r, int kbyte) {
    uint32_t seg = ((uint32_t)(kbyte >> 4)) ^ (((uint32_t)r >> 1) & 3u);
    return (uint32_t)r * 64u + (seg << 4) + (uint32_t)(kbyte & 15);
}

// ---------------- RoPE tables ----------------
__global__ void rope_tables_kernel(const int* __restrict__ pos_ids) {
    int s = blockIdx.x;
    int d = threadIdx.x;
    double inv = pow(10000.0, -(double)(2 * d) / 128.0);
    double ang = (double)pos_ids[s] * inv;
    g_cos[s * 64 + d] = (float)cos(ang);
    g_sin[s * 64 + d] = (float)sin(ang);
}

// ---------------- fp32 -> bf16 hi/lo split ----------------
__global__ __launch_bounds__(256)
void split_kernel(const float* __restrict__ X, __nv_bfloat16* __restrict__ H,
                  __nv_bfloat16* __restrict__ L) {
    int i = (blockIdx.x * 256 + threadIdx.x) * 4;
    float4 v = *(const float4*)(X + i);
    __nv_bfloat16 h0 = __float2bfloat16(v.x), h1 = __float2bfloat16(v.y);
    __nv_bfloat16 h2 = __float2bfloat16(v.z), h3 = __float2bfloat16(v.w);
    H[i + 0] = h0; H[i + 1] = h1; H[i + 2] = h2; H[i + 3] = h3;
    L[i + 0] = __float2bfloat16(v.x - __bfloat162float(h0));
    L[i + 1] = __float2bfloat16(v.y - __bfloat162float(h1));
    L[i + 2] = __float2bfloat16(v.z - __bfloat162float(h2));
    L[i + 3] = __float2bfloat16(v.w - __bfloat162float(h3));
}

// ---------------- dequant + transpose: W[k,n] -> B[n,k] bf16 hi/lo ----------------
__global__ __launch_bounds__(256)
void dequant_transpose_kernel(const int* __restrict__ Qw, const float* __restrict__ Sc,
                              const float* __restrict__ Zr, __nv_bfloat16* __restrict__ Bh,
                              __nv_bfloat16* __restrict__ Bl, int K, int N) {
    __shared__ float w[32][33];
    int n0 = blockIdx.x * 32, k0 = blockIdx.y * 32;
    int tx = threadIdx.x & 31, ty = threadIdx.x >> 5;
    int g = k0 >> 7;
    float s = Sc[(size_t)g * N + n0 + tx];
    float z = Zr[(size_t)g * N + n0 + tx];
    #pragma unroll
    for (int rr = 0; rr < 32; rr += 8) {
        int q = Qw[(size_t)(k0 + rr + ty) * N + n0 + tx];
        w[rr + ty][tx] = ((float)q - z) * s;
    }
    __syncthreads();
    #pragma unroll
    for (int rr = 0; rr < 32; rr += 8) {
        int n = rr + ty;
        float v = w[tx][n];
        __nv_bfloat16 h = __float2bfloat16(v);
        size_t o = (size_t)(n0 + n) * K + k0 + tx;
        Bh[o] = h;
        Bl[o] = __float2bfloat16(v - __bfloat162float(h));
    }
}

// ---------------- bf16x3 mma.sync GEMM, CTA 128x256, warp 64x64, 3-stage ----------------
// grid.x = M tiles (fast -> L2-friendly: wave shares B columns), grid.y = N tiles
#define GST_AH 0
#define GST_AL 8192
#define GST_BH 16384
#define GST_BL 32768
#define GSTAGE 49152

__global__ __launch_bounds__(256, 1)
void gemm_mma_kernel(const __nv_bfloat16* __restrict__ Ah,
                     const __nv_bfloat16* __restrict__ Al,
                     const __nv_bfloat16* __restrict__ Bh,
                     const __nv_bfloat16* __restrict__ Bl,
                     float* __restrict__ C, int M, int N, int K) {
    extern __shared__ char smraw[];
    const uint32_t sb = smem_to_u32(smraw);
    const int tid = threadIdx.x, lane = tid & 31, wid = tid >> 5;
    const int m0 = blockIdx.x << 7, n0 = blockIdx.y << 8;
    const int wm = (wid & 1) << 6;     // 0 / 64
    const int wn = (wid >> 1) << 6;    // 0 / 64 / 128 / 192

    float acc[4][8][4];
    #pragma unroll
    for (int mi = 0; mi < 4; mi++)
        #pragma unroll
        for (int ni = 0; ni < 8; ni++)
            #pragma unroll
            for (int e = 0; e < 4; e++) acc[mi][ni][e] = 0.f;

    auto load_stage = [&](int buf, int k0) {
        uint32_t stage = sb + (uint32_t)buf * GSTAGE;
        #pragma unroll
        for (int u = 0; u < 4; u++) {               // A hi+lo: 1024 x 16B
            int idx = tid + u * 256;
            int hl = idx >> 9;
            int r = (idx & 511) >> 2, seg = idx & 3;
            const __nv_bfloat16* src = hl ? Al : Ah;
            cp_async16(stage + (hl ? GST_AL : GST_AH) + swz(r, seg << 4),
                       src + (size_t)(m0 + r) * K + k0 + seg * 8);
        }
        #pragma unroll
        for (int u = 0; u < 8; u++) {               // B hi+lo: 2048 x 16B
            int idx = tid + u * 256;
            int hl = idx >> 10;
            int r = (idx & 1023) >> 2, seg = idx & 3;
            const __nv_bfloat16* src = hl ? Bl : Bh;
            cp_async16(stage + (hl ? GST_BL : GST_BH) + swz(r, seg << 4),
                       src + (size_t)(n0 + r) * K + k0 + seg * 8);
        }
        CP_COMMIT();
    };

    const int NCH = K >> 5;
    load_stage(0, 0);
    load_stage(1, 32);

    int buf = 0;
    for (int i = 0; i < NCH; i++) {
        if (i + 2 < NCH) {
            int nb = buf + 2; if (nb >= 3) nb -= 3;
            load_stage(nb, (i + 2) << 5);
            CP_WAIT(2);
        } else if (i + 1 < NCH) {
            CP_WAIT(1);
        } else {
            CP_WAIT(0);
        }
        __syncthreads();

        uint32_t stage = sb + (uint32_t)buf * GSTAGE;
        #pragma unroll
        for (int ks = 0; ks < 2; ks++) {
            uint32_t a_h[4][4], a_l[4][4];
            int akb = ks * 32 + ((lane >> 4) & 1) * 16;
            #pragma unroll
            for (int mi = 0; mi < 4; mi++) {
                int row = wm + mi * 16 + (lane & 15);
                uint32_t so = swz(row, akb);
                LDSM_X4(a_h[mi], stage + GST_AH + so);
                LDSM_X4(a_l[mi], stage + GST_AL + so);
            }
            int bkb = ks * 32 + ((lane >> 3) & 1) * 16;
            #pragma unroll
            for (int ni = 0; ni < 8; ni++) {
                uint32_t b_h[2], b_l[2];
                int row = wn + ni * 8 + (lane & 7);
                uint32_t so = swz(row, bkb);
                LDSM_X2(b_h, stage + GST_BH + so);
                LDSM_X2(b_l, stage + GST_BL + so);
                #pragma unroll
                for (int mi = 0; mi < 4; mi++) {
                    MMA_BF16(acc[mi][ni], a_h[mi], b_h);
                    MMA_BF16(acc[mi][ni], a_l[mi], b_h);
                    MMA_BF16(acc[mi][ni], a_h[mi], b_l);
                }
            }
        }
        __syncthreads();
        if (++buf == 3) buf = 0;
    }

    const int er = m0 + wm + (lane >> 2);
    const int ec = n0 + wn + (lane & 3) * 2;
    #pragma unroll
    for (int mi = 0; mi < 4; mi++) {
        #pragma unroll
        for (int ni = 0; ni < 8; ni++) {
            float* p = C + (size_t)(er + mi * 16) * N + ec + ni * 8;
            *(float2*)p                   = make_float2(acc[mi][ni][0], acc[mi][ni][1]);
            *(float2*)(p + 8 * (size_t)N) = make_float2(acc[mi][ni][2], acc[mi][ni][3]);
        }
    }
}

// ---------------- RoPE + split Q/K -> bf16 hi/lo [h][s][d] (scale folded into Q) ------
__global__ __launch_bounds__(256)
void rope_split_kernel() {
    int s = blockIdx.x;
    const float* row = g_proj + (size_t)s * QKVN;
    for (int it = threadIdx.x; it < 4096; it += 256) {
        int qk = it >> 11;                 // 0=q, 1=k
        int hh = (it >> 6) & 31;
        int d  = it & 63;
        float c = g_cos[s * 64 + d], sn = g_sin[s * 64 + d];
        const float* p = row + qk * HID + hh * 128;
        float x1 = p[d], x2 = p[d + 64];
        float y1 = x1 * c - x2 * sn;
        float y2 = x2 * c + x1 * sn;
        if (qk == 0) { y1 *= 0.08838834764831845f; y2 *= 0.08838834764831845f; }
        __nv_bfloat16* H = qk ? g_kh : g_qh;
        __nv_bfloat16* L = qk ? g_kl : g_ql;
        size_t o = ((size_t)hh * SEQ + s) * 128 + d;
        __nv_bfloat16 h1 = __float2bfloat16(y1), h2 = __float2bfloat16(y2);
        H[o] = h1; H[o + 64] = h2;
        L[o]      = __float2bfloat16(y1 - __bfloat162float(h1));
        L[o + 64] = __float2bfloat16(y2 - __bfloat162float(h2));
    }
}

// ---------------- V transpose + split: [s][h*128+d] -> [h][d][s] bf16 hi/lo ------------
__global__ void v_transpose_split_kernel() {
    __shared__ float t[32][33];
    int s0 = blockIdx.x * 32, d0 = blockIdx.y * 32, h = blockIdx.z;
    int tx = threadIdx.x, ty = threadIdx.y;       // 32 x 8
    #pragma unroll
    for (int rr = 0; rr < 32; rr += 8)
        t[rr + ty][tx] = g_proj[(size_t)(s0 + rr + ty) * QKVN + 2 * HID + h * 128 + d0 + tx];
    __syncthreads();
    #pragma unroll
    for (int rr = 0; rr < 32; rr += 8) {
        int d = d0 + rr + ty;
        float v = t[tx][rr + ty];
        __nv_bfloat16 hi = __float2bfloat16(v);
        size_t o = ((size_t)h * 128 + d) * SEQ + s0 + tx;
        g_vth[o] = hi;
        g_vtl[o] = __float2bfloat16(v - __bfloat162float(hi));
    }
}

// ---------------- bf16x3 mma.sync flash attention (causal) — validated R5 --------------
#define QPITCH 272
#define VPITCH 144
#define AT_QH  0
#define AT_QL  17408
#define AT_K0  34816
#define KV_KH  0
#define KV_KL  17408
#define KV_VH  34816
#define KV_VL  53248
#define AT_STAGE 71680
#define AT_SMEM  (AT_K0 + 2 * AT_STAGE)   // 178176

__global__ __launch_bounds__(128, 1)
void attn_mma_kernel(float* __restrict__ out) {
    extern __shared__ char smraw[];
    const uint32_t sb = smem_to_u32(smraw);
    const int h  = blockIdx.x;
    const int qt = (int)gridDim.y - 1 - (int)blockIdx.y;   // big tiles first
    const int tid = threadIdx.x, lane = tid & 31, warp = tid >> 5;
    const int wm16 = warp << 4;

    const __nv_bfloat16* qhp = g_qh + ((size_t)h * SEQ + qt * 64) * 128;
    const __nv_bfloat16* qlp = g_ql + ((size_t)h * SEQ + qt * 64) * 128;
    const __nv_bfloat16* kh0 = g_kh + (size_t)h * SEQ * 128;
    const __nv_bfloat16* kl0 = g_kl + (size_t)h * SEQ * 128;
    const __nv_bfloat16* vh0 = g_vth + (size_t)h * 128 * SEQ;
    const __nv_bfloat16* vl0 = g_vtl + (size_t)h * 128 * SEQ;

    auto load_kv = [&](int kt_, int buf_) {
        uint32_t base = sb + AT_K0 + (uint32_t)buf_ * AT_STAGE;
        const __nv_bfloat16* kh = kh0 + (size_t)kt_ * 64 * 128;
        const __nv_bfloat16* kl = kl0 + (size_t)kt_ * 64 * 128;
        #pragma unroll
        for (int u = 0; u < 16; u++) {
            int i = tid + u * 128;
            int m = i >> 10, c = i & 1023, r = c >> 4, seg = c & 15;
            cp_async16(base + m * 17408 + r * QPITCH + seg * 16,
                       (m ? kl : kh) + r * 128 + seg * 8);
        }
        const __nv_bfloat16* vh = vh0 + kt_ * 64;
        const __nv_bfloat16* vl = vl0 + kt_ * 64;
        #pragma unroll
        for (int u = 0; u < 16; u++) {
            int i = tid + u * 128;
            int m = i >> 10, c = i & 1023, r = c >> 3, seg = c & 7;
            cp_async16(base + KV_VH + m * 18432 + r * VPITCH + seg * 16,
                       (m ? vl : vh) + (size_t)r * SEQ + seg * 8);
        }
    };

    #pragma unroll
    for (int u = 0; u < 16; u++) {
        int i = tid + u * 128;
        int m = i >> 10, c = i & 1023, r = c >> 4, seg = c & 15;
        const __nv_bfloat16* src = m ? qlp : qhp;
        cp_async16(sb + (m ? AT_QL : AT_QH) + r * QPITCH + seg * 16,
                   src + r * 128 + seg * 8);
    }
    load_kv(0, 0);
    CP_COMMIT();

    float o[16][4];
    #pragma unroll
    for (int n = 0; n < 16; n++)
        #pragma unroll
        for (int e = 0; e < 4; e++) o[n][e] = 0.f;
    float m0 = neg_inf(), m1 = neg_inf(), l0 = 0.f, l1 = 0.f;

    for (int kt = 0; kt <= qt; kt++) {
        int buf = kt & 1;
        if (kt < qt) {
            load_kv(kt + 1, buf ^ 1);
            CP_COMMIT();
            CP_WAIT(1);
        } else {
            CP_WAIT(0);
        }
        __syncthreads();

        uint32_t kvb = sb + AT_K0 + (uint32_t)buf * AT_STAGE;

        float s4[8][4];
        #pragma unroll
        for (int j = 0; j < 8; j++)
            #pragma unroll
            for (int e = 0; e < 4; e++) s4[j][e] = 0.f;
        #pragma unroll
        for (int ks = 0; ks < 8; ks++) {
            uint32_t ah[4], al[4];
            uint32_t qa = (uint32_t)(wm16 + (lane & 15)) * QPITCH
                        + ks * 32 + ((lane >> 4) & 1) * 16;
            LDSM_X4(ah, sb + AT_QH + qa);
            LDSM_X4(al, sb + AT_QL + qa);
            #pragma unroll
            for (int j = 0; j < 8; j++) {
                uint32_t bh[2], bl[2];
                uint32_t ka = (uint32_t)(j * 8 + (lane & 7)) * QPITCH
                            + ks * 32 + ((lane >> 3) & 1) * 16;
                LDSM_X2(bh, kvb + KV_KH + ka);
                LDSM_X2(bl, kvb + KV_KL + ka);
                MMA_BF16(s4[j], ah, bh);
                MMA_BF16(s4[j], al, bh);
                MMA_BF16(s4[j], ah, bl);
            }
        }

        if (kt == qt) {
            int colb = 2 * (lane & 3);
            int rowb = wm16 + (lane >> 2);
            #pragma unroll
            for (int j = 0; j < 8; j++) {
                int c0 = j * 8 + colb;
                if (c0     > rowb)     s4[j][0] = neg_inf();
                if (c0 + 1 > rowb)     s4[j][1] = neg_inf();
                if (c0     > rowb + 8) s4[j][2] = neg_inf();
                if (c0 + 1 > rowb + 8) s4[j][3] = neg_inf();
            }
        }

        float tm0 = neg_inf(), tm1 = neg_inf();
        #pragma unroll
        for (int j = 0; j < 8; j++) {
            tm0 = fmaxf(tm0, fmaxf(s4[j][0], s4[j][1]));
            tm1 = fmaxf(tm1, fmaxf(s4[j][2], s4[j][3]));
        }
        tm0 = fmaxf(tm0, __shfl_xor_sync(0xffffffffu, tm0, 1));
        tm0 = fmaxf(tm0, __shfl_xor_sync(0xffffffffu, tm0, 2));
        tm1 = fmaxf(tm1, __shfl_xor_sync(0xffffffffu, tm1, 1));
        tm1 = fmaxf(tm1, __shfl_xor_sync(0xffffffffu, tm1, 2));
        float mn0 = fmaxf(m0, tm0), mn1 = fmaxf(m1, tm1);
        float a0 = __expf(m0 - mn0), a1 = __expf(m1 - mn1);
        m0 = mn0; m1 = mn1;

        float rs0 = 0.f, rs1 = 0.f;
        uint32_t pah[4][4], pal[4][4];
        #pragma unroll
        for (int j = 0; j < 8; j++) {
            float p0 = __expf(s4[j][0] - mn0), p1 = __expf(s4[j][1] - mn0);
            float p2 = __expf(s4[j][2] - mn1), p3 = __expf(s4[j][3] - mn1);
            rs0 += p0 + p1; rs1 += p2 + p3;
            __nv_bfloat16 b0 = __float2bfloat16(p0), b1 = __float2bfloat16(p1);
            __nv_bfloat16 b2 = __float2bfloat16(p2), b3 = __float2bfloat16(p3);
            uint32_t h01 = ((uint32_t)__bfloat16_as_ushort(b1) << 16) | __bfloat16_as_ushort(b0);
            uint32_t h23 = ((uint32_t)__bfloat16_as_ushort(b3) << 16) | __bfloat16_as_ushort(b2);
            __nv_bfloat16 c0 = __float2bfloat16(p0 - __bfloat162float(b0));
            __nv_bfloat16 c1 = __float2bfloat16(p1 - __bfloat162float(b1));
            __nv_bfloat16 c2 = __float2bfloat16(p2 - __bfloat162float(b2));
            __nv_bfloat16 c3 = __float2bfloat16(p3 - __bfloat162float(b3));
            uint32_t l01 = ((uint32_t)__bfloat16_as_ushort(c1) << 16) | __bfloat16_as_ushort(c0);
            uint32_t l23 = ((uint32_t)__bfloat16_as_ushort(c3) << 16) | __bfloat16_as_ushort(c2);
            int k2 = j >> 1, odd = (j & 1) << 1;
            pah[k2][odd] = h01; pah[k2][odd + 1] = h23;
            pal[k2][odd] = l01; pal[k2][odd + 1] = l23;
        }
        rs0 += __shfl_xor_sync(0xffffffffu, rs0, 1);
        rs0 += __shfl_xor_sync(0xffffffffu, rs0, 2);
        rs1 += __shfl_xor_sync(0xffffffffu, rs1, 1);
        rs1 += __shfl_xor_sync(0xffffffffu, rs1, 2);
        l0 = l0 * a0 + rs0;
        l1 = l1 * a1 + rs1;
        #pragma unroll
        for (int n = 0; n < 16; n++) {
            o[n][0] *= a0; o[n][1] *= a0; o[n][2] *= a1; o[n][3] *= a1;
        }

        #pragma unroll
        for (int ks2 = 0; ks2 < 4; ks2++) {
            #pragma unroll
            for (int n = 0; n < 16; n++) {
                uint32_t vh[2], vl[2];
                uint32_t va = (uint32_t)(n * 8 + (lane & 7)) * VPITCH
                            + ks2 * 32 + ((lane >> 3) & 1) * 16;
                LDSM_X2(vh, kvb + KV_VH + va);
                LDSM_X2(vl, kvb + KV_VL + va);
                MMA_BF16(o[n], pah[ks2], vh);
                MMA_BF16(o[n], pal[ks2], vh);
                MMA_BF16(o[n], pah[ks2], vl);
            }
        }
        __syncthreads();
    }

    float inv0 = 1.f / l0, inv1 = 1.f / l1;
    int rg = qt * 64 + wm16 + (lane >> 2);
    int cb = h * 128 + 2 * (lane & 3);
    #pragma unroll
    for (int n = 0; n < 16; n++) {
        float* p0 = out + (size_t)rg * HID + cb + n * 8;
        *(float2*)p0 = make_float2(o[n][0] * inv0, o[n][1] * inv0);
        float* p1 = out + (size_t)(rg + 8) * HID + cb + n * 8;
        *(float2*)p1 = make_float2(o[n][2] * inv1, o[n][3] * inv1);
    }
}

extern "C" void kernel_launch(void* const* d_in, const int* in_sizes, int n_in,
                              void* d_out, int out_size) {
    const float* hidden = (const float*)d_in[0];
    const int*   pos    = (const int*)d_in[1];
    const int*   qkv_qw = (const int*)d_in[2];
    const float* qkv_s  = (const float*)d_in[3];
    const float* qkv_z  = (const float*)d_in[4];
    const int*   o_qw   = (const int*)d_in[5];
    const float* o_s    = (const float*)d_in[6];
    const float* o_z    = (const float*)d_in[7];
    float* out = (float*)d_out;

    void* p;
    cudaGetSymbolAddress(&p, g_proj); float* proj = (float*)p;
    cudaGetSymbolAddress(&p, g_attn); float* attn = (float*)p;
    cudaGetSymbolAddress(&p, g_ah);   __nv_bfloat16* ah = (__nv_bfloat16*)p;
    cudaGetSymbolAddress(&p, g_al);   __nv_bfloat16* al = (__nv_bfloat16*)p;
    cudaGetSymbolAddress(&p, g_bh);   __nv_bfloat16* bh = (__nv_bfloat16*)p;
    cudaGetSymbolAddress(&p, g_bl);   __nv_bfloat16* bl = (__nv_bfloat16*)p;

    int gemm_smem = 3 * GSTAGE;                       // 147456
    cudaFuncSetAttribute(gemm_mma_kernel,
                         cudaFuncAttributeMaxDynamicSharedMemorySize, gemm_smem);
    cudaFuncSetAttribute(attn_mma_kernel,
                         cudaFuncAttributeMaxDynamicSharedMemorySize, AT_SMEM);

    // 1. RoPE tables
    rope_tables_kernel<<<SEQ, 64>>>(pos);

    // 2. split activations; dequant+transpose QKV weights
    split_kernel<<<(SEQ * HID) / (256 * 4), 256>>>(hidden, ah, al);
    dequant_transpose_kernel<<<dim3(QKVN / 32, HID / 32), 256>>>(
        qkv_qw, qkv_s, qkv_z, bh, bl, HID, QKVN);

    // 3. QKV projection  (grid.x = M tiles, grid.y = N tiles)
    gemm_mma_kernel<<<dim3(SEQ / 128, QKVN / 256), 256, gemm_smem>>>(
        ah, al, bh, bl, proj, SEQ, QKVN, HID);

    // 4. RoPE + split Q/K; transpose + split V
    rope_split_kernel<<<SEQ, 256>>>();
    v_transpose_split_kernel<<<dim3(SEQ / 32, HDIM / 32, HEADS), dim3(32, 8)>>>();

    // 5. causal flash attention on tensor cores
    attn_mma_kernel<<<dim3(HEADS, SEQ / 64), 128, AT_SMEM>>>(attn);

    // 6. split attention output; dequant+transpose O weights
    split_kernel<<<(SEQ * HID) / (256 * 4), 256>>>(attn, ah, al);
    dequant_transpose_kernel<<<dim3(HID / 32, HID / 32), 256>>>(
        o_qw, o_s, o_z, bh, bl, HID, HID);

    // 7. output projection
    gemm_mma_kernel<<<dim3(SEQ / 128, HID / 256), 256, gemm_smem>>>(
        ah, al, bh, bl, out, SEQ, HID, HID);
}

// round 7
// speedup vs baseline: 3.5096x; 1.2397x over previous
#include <cuda_runtime.h>
#include <cuda_bf16.h>
#include <cuda_fp16.h>
#include <math.h>
#include <stdint.h>

#define SEQ   2048
#define HID   4096
#define HEADS 32
#define HDIM  128
#define QKVN  12288
#define KPAD  4160          // 4096 + 64 ext cols (zero-correction)
#define NCH   130           // KPAD / 32

// ---------------- scratch (device globals; no runtime allocation) ----------------
__device__ float g_proj[(size_t)SEQ * QKVN];
__device__ float g_attn[(size_t)SEQ * HID];
__device__ float g_cos[SEQ * 64];
__device__ float g_sin[SEQ * 64];
__device__ float g_R[(size_t)32 * QKVN];                      // telescoping ratios
__device__ __half g_ah[(size_t)SEQ * KPAD];                   // activation hi (fp16)
__device__ __half g_al[(size_t)SEQ * KPAD];                   // activation lo
__device__ __half g_bq[(size_t)QKVN * KPAD];                  // exact q^T + ext cols
__device__ __nv_bfloat16 g_qh[(size_t)HEADS * SEQ * HDIM];
__device__ __nv_bfloat16 g_ql[(size_t)HEADS * SEQ * HDIM];
__device__ __nv_bfloat16 g_kh[(size_t)HEADS * SEQ * HDIM];
__device__ __nv_bfloat16 g_kl[(size_t)HEADS * SEQ * HDIM];
__device__ __nv_bfloat16 g_vth[(size_t)HEADS * HDIM * SEQ];
__device__ __nv_bfloat16 g_vtl[(size_t)HEADS * HDIM * SEQ];

__device__ __forceinline__ float neg_inf() { return __int_as_float(0xff800000); }

__device__ __forceinline__ uint32_t smem_to_u32(const void* p) {
    uint32_t a;
    asm("{ .reg .u64 t; cvta.to.shared.u64 t, %1; cvt.u32.u64 %0, t; }" : "=r"(a) : "l"(p));
    return a;
}
__device__ __forceinline__ void cp_async16(uint32_t dst, const void* src) {
    asm volatile("cp.async.cg.shared.global [%0], [%1], 16;" :: "r"(dst), "l"(src));
}
#define CP_COMMIT() asm volatile("cp.async.commit_group;" ::: "memory")
#define CP_WAIT(n)  asm volatile("cp.async.wait_group %0;" :: "n"(n) : "memory")

#define LDSM_X4(r, a) \
    asm volatile("ldmatrix.sync.aligned.m8n8.x4.shared.b16 {%0,%1,%2,%3}, [%4];" \
        : "=r"((r)[0]), "=r"((r)[1]), "=r"((r)[2]), "=r"((r)[3]) : "r"(a))
#define LDSM_X2(r, a) \
    asm volatile("ldmatrix.sync.aligned.m8n8.x2.shared.b16 {%0,%1}, [%2];" \
        : "=r"((r)[0]), "=r"((r)[1]) : "r"(a))
#define MMA_BF16(d, a, b) \
    asm volatile("mma.sync.aligned.m16n8k16.row.col.f32.bf16.bf16.f32 " \
        "{%0,%1,%2,%3}, {%4,%5,%6,%7}, {%8,%9}, {%0,%1,%2,%3};" \
        : "+f"((d)[0]), "+f"((d)[1]), "+f"((d)[2]), "+f"((d)[3]) \
        : "r"((a)[0]), "r"((a)[1]), "r"((a)[2]), "r"((a)[3]), "r"((b)[0]), "r"((b)[1]))
#define MMA_F16(d, a, b) \
    asm volatile("mma.sync.aligned.m16n8k16.row.col.f32.f16.f16.f32 " \
        "{%0,%1,%2,%3}, {%4,%5,%6,%7}, {%8,%9}, {%0,%1,%2,%3};" \
        : "+f"((d)[0]), "+f"((d)[1]), "+f"((d)[2]), "+f"((d)[3]) \
        : "r"((a)[0]), "r"((a)[1]), "r"((a)[2]), "r"((a)[3]), "r"((b)[0]), "r"((b)[1]))

__device__ __forceinline__ uint32_t swz(int r, int kbyte) {
    uint32_t seg = ((uint32_t)(kbyte >> 4)) ^ (((uint32_t)r >> 1) & 3u);
    return (uint32_t)r * 64u + (seg << 4) + (uint32_t)(kbyte & 15);
}

// ---------------- RoPE tables ----------------
__global__ void rope_tables_kernel(const int* __restrict__ pos_ids) {
    int s = blockIdx.x;
    int d = threadIdx.x;
    double inv = pow(10000.0, -(double)(2 * d) / 128.0);
    double ang = (double)pos_ids[s] * inv;
    g_cos[s * 64 + d] = (float)cos(ang);
    g_sin[s * 64 + d] = (float)sin(ang);
}

// ---------------- fp32 -> fp16 hi/lo split into padded [M][KPAD] ----------------
__global__ __launch_bounds__(256)
void split_pad_kernel(const float* __restrict__ X, __half* __restrict__ H,
                      __half* __restrict__ L) {
    int i = (blockIdx.x * 256 + threadIdx.x) * 4;
    int r = i >> 12, c = i & 4095;
    float4 v = *(const float4*)(X + i);
    size_t o = (size_t)r * KPAD + c;
    __half h0 = __float2half_rn(v.x), h1 = __float2half_rn(v.y);
    __half h2 = __float2half_rn(v.z), h3 = __float2half_rn(v.w);
    H[o + 0] = h0; H[o + 1] = h1; H[o + 2] = h2; H[o + 3] = h3;
    L[o + 0] = __float2half_rn(v.x - __half2float(h0));
    L[o + 1] = __float2half_rn(v.y - __half2float(h1));
    L[o + 2] = __float2half_rn(v.z - __half2float(h2));
    L[o + 3] = __float2half_rn(v.w - __half2float(h3));
}

// ---------------- per-row per-group sums -> ext cols of A ----------------
__global__ __launch_bounds__(256)
void rowsum_ext_kernel(const float* __restrict__ X, __half* __restrict__ H,
                       __half* __restrict__ L) {
    __shared__ float gs[32];
    int m = blockIdx.x;
    const float* row = X + (size_t)m * 4096;
    int g = threadIdx.x >> 3, l8 = threadIdx.x & 7;
    float s = 0.f;
    #pragma unroll
    for (int j = 0; j < 16; j++) s += row[g * 128 + l8 * 16 + j];
    s += __shfl_xor_sync(0xffffffffu, s, 1);
    s += __shfl_xor_sync(0xffffffffu, s, 2);
    s += __shfl_xor_sync(0xffffffffu, s, 4);
    if (l8 == 0) gs[g] = s;
    __syncthreads();
    if (threadIdx.x < 32) {
        float v = gs[threadIdx.x];
        __half h = __float2half_rn(v);
        __half lo = __float2half_rn(v - __half2float(h));
        size_t o = (size_t)m * KPAD + 4096 + threadIdx.x;
        H[o] = h; H[o + 32] = h;          // duplicated for ext-hi and ext-lo B blocks
        L[o] = lo; L[o + 32] = lo;
    }
}

// ---------------- q transpose: int32 [K][N] -> exact fp16 [N][KPAD] ----------------
__global__ __launch_bounds__(256)
void qT_kernel(const int* __restrict__ Qw, __half* __restrict__ B, int N) {
    __shared__ int w[32][33];
    int n0 = blockIdx.x * 32, k0 = blockIdx.y * 32;
    int tx = threadIdx.x & 31, ty = threadIdx.x >> 5;
    #pragma unroll
    for (int rr = 0; rr < 32; rr += 8)
        w[rr + ty][tx] = Qw[(size_t)(k0 + rr + ty) * N + n0 + tx];
    __syncthreads();
    #pragma unroll
    for (int rr = 0; rr < 32; rr += 8)
        B[(size_t)(n0 + rr + ty) * KPAD + k0 + tx] =
            __float2half_rn((float)w[tx][rr + ty]);
}

// ---------------- scale prep: R ratios + ext B cols (-s*z hi/lo) ----------------
__global__ void prep_scales_kernel(const float* __restrict__ S, const float* __restrict__ Z,
                                   float* __restrict__ R, __half* __restrict__ B, int N) {
    int n = blockIdx.x * 256 + threadIdx.x;
    if (n >= N) return;
    float sp[32];
    #pragma unroll
    for (int g = 0; g < 32; g++) sp[g] = fmaxf(S[g * N + n], 1e-30f);
    #pragma unroll
    for (int g = 0; g < 31; g++) R[g * N + n] = sp[g] / sp[g + 1];
    R[31 * N + n] = sp[31];
    #pragma unroll
    for (int g = 0; g < 32; g++) {
        float t = -S[g * N + n] * Z[g * N + n];
        __half th = __float2half_rn(t);
        __half tl = __float2half_rn(t - __half2float(th));
        B[(size_t)n * KPAD + 4096 + g] = th;
        B[(size_t)n * KPAD + 4128 + g] = tl;
    }
}

// ---------------- exact-q fp16 GEMM with telescoping group rescale ----------------
// C[M,N] = sum_g s_g * ( (Ah+Al) @ q^T )_g  + X @ (-s*z)   (ext cols), fp32 acc
// CTA 128x256, warp 64x64, BK=32, 3-stage cp.async. grid.x = M tiles (L2 raster).
#define GST_AH 0
#define GST_AL 8192
#define GST_B  16384
#define GSTAGE 32768

__global__ __launch_bounds__(256, 1)
void gemm_q_kernel(const __half* __restrict__ Ah, const __half* __restrict__ Al,
                   const __half* __restrict__ B, const float* __restrict__ R,
                   float* __restrict__ C, int M, int N) {
    extern __shared__ char smraw[];
    const uint32_t sb = smem_to_u32(smraw);
    const int tid = threadIdx.x, lane = tid & 31, wid = tid >> 5;
    const int m0 = blockIdx.x << 7, n0 = blockIdx.y << 8;
    const int wm = (wid & 1) << 6;
    const int wn = (wid >> 1) << 6;

    float acc[4][8][4];
    #pragma unroll
    for (int mi = 0; mi < 4; mi++)
        #pragma unroll
        for (int ni = 0; ni < 8; ni++)
            #pragma unroll
            for (int e = 0; e < 4; e++) acc[mi][ni][e] = 0.f;

    auto load_stage = [&](int buf, int c) {
        uint32_t stage = sb + (uint32_t)buf * GSTAGE;
        int k0 = c << 5;
        #pragma unroll
        for (int u = 0; u < 4; u++) {               // A hi+lo: 1024 x 16B
            int idx = tid + u * 256;
            int hl = idx >> 9;
            int r = (idx & 511) >> 2, seg = idx & 3;
            const __half* src = hl ? Al : Ah;
            cp_async16(stage + (hl ? GST_AL : GST_AH) + swz(r, seg << 4),
                       src + (size_t)(m0 + r) * KPAD + k0 + seg * 8);
        }
        #pragma unroll
        for (int u = 0; u < 4; u++) {               // B: 1024 x 16B (256 rows)
            int idx = tid + u * 256;
            int r = idx >> 2, seg = idx & 3;
            cp_async16(stage + GST_B + swz(r, seg << 4),
                       B + (size_t)(n0 + r) * KPAD + k0 + seg * 8);
        }
        CP_COMMIT();
    };

    load_stage(0, 0);
    load_stage(1, 1);

    float rv[16];
    int buf = 0;
    for (int i = 0; i < NCH; i++) {
        if (i + 2 < NCH) {
            int nb = buf + 2; if (nb >= 3) nb -= 3;
            load_stage(nb, i + 2);
            CP_WAIT(2);
        } else if (i + 1 < NCH) {
            CP_WAIT(1);
        } else {
            CP_WAIT(0);
        }
        __syncthreads();

        // prefetch rescale row 3 chunks ahead of use
        if ((i & 3) == 0 && i < 128) {
            int g = i >> 2;
            #pragma unroll
            for (int j = 0; j < 16; j++)
                rv[j] = __ldg(&R[(size_t)g * N + n0 + wn + (j >> 1) * 8
                                 + (lane & 3) * 2 + (j & 1)]);
        }

        uint32_t stage = sb + (uint32_t)buf * GSTAGE;
        #pragma unroll
        for (int ks = 0; ks < 2; ks++) {
            uint32_t a_h[4][4], a_l[4][4];
            int akb = ks * 32 + ((lane >> 4) & 1) * 16;
            #pragma unroll
            for (int mi = 0; mi < 4; mi++) {
                int row = wm + mi * 16 + (lane & 15);
                uint32_t so = swz(row, akb);
                LDSM_X4(a_h[mi], stage + GST_AH + so);
                LDSM_X4(a_l[mi], stage + GST_AL + so);
            }
            int bkb = ks * 32 + ((lane >> 3) & 1) * 16;
            #pragma unroll
            for (int ni = 0; ni < 8; ni++) {
                uint32_t b[2];
                int row = wn + ni * 8 + (lane & 7);
                LDSM_X2(b, stage + GST_B + swz(row, bkb));
                #pragma unroll
                for (int mi = 0; mi < 4; mi++) {
                    MMA_F16(acc[mi][ni], a_h[mi], b);
                    MMA_F16(acc[mi][ni], a_l[mi], b);
                }
            }
        }

        // group boundary: acc *= s_g / s_{g+1}  (last group: *= s_31)
        if ((i & 3) == 3 && i < 128) {
            #pragma unroll
            for (int mi = 0; mi < 4; mi++)
                #pragma unroll
                for (int ni = 0; ni < 8; ni++) {
                    acc[mi][ni][0] *= rv[ni * 2];
                    acc[mi][ni][1] *= rv[ni * 2 + 1];
                    acc[mi][ni][2] *= rv[ni * 2];
                    acc[mi][ni][3] *= rv[ni * 2 + 1];
                }
        }
        __syncthreads();
        if (++buf == 3) buf = 0;
    }

    const int er = m0 + wm + (lane >> 2);
    const int ec = n0 + wn + (lane & 3) * 2;
    #pragma unroll
    for (int mi = 0; mi < 4; mi++) {
        #pragma unroll
        for (int ni = 0; ni < 8; ni++) {
            float* p = C + (size_t)(er + mi * 16) * N + ec + ni * 8;
            *(float2*)p                   = make_float2(acc[mi][ni][0], acc[mi][ni][1]);
            *(float2*)(p + 8 * (size_t)N) = make_float2(acc[mi][ni][2], acc[mi][ni][3]);
        }
    }
}

// ---------------- RoPE + split Q/K -> bf16 hi/lo [h][s][d] ----------------
__global__ __launch_bounds__(256)
void rope_split_kernel() {
    int s = blockIdx.x;
    const float* row = g_proj + (size_t)s * QKVN;
    for (int it = threadIdx.x; it < 4096; it += 256) {
        int qk = it >> 11;
        int hh = (it >> 6) & 31;
        int d  = it & 63;
        float c = g_cos[s * 64 + d], sn = g_sin[s * 64 + d];
        const float* p = row + qk * HID + hh * 128;
        float x1 = p[d], x2 = p[d + 64];
        float y1 = x1 * c - x2 * sn;
        float y2 = x2 * c + x1 * sn;
        if (qk == 0) { y1 *= 0.08838834764831845f; y2 *= 0.08838834764831845f; }
        __nv_bfloat16* H = qk ? g_kh : g_qh;
        __nv_bfloat16* L = qk ? g_kl : g_ql;
        size_t o = ((size_t)hh * SEQ + s) * 128 + d;
        __nv_bfloat16 h1 = __float2bfloat16(y1), h2 = __float2bfloat16(y2);
        H[o] = h1; H[o + 64] = h2;
        L[o]      = __float2bfloat16(y1 - __bfloat162float(h1));
        L[o + 64] = __float2bfloat16(y2 - __bfloat162float(h2));
    }
}

// ---------------- V transpose + split ----------------
__global__ void v_transpose_split_kernel() {
    __shared__ float t[32][33];
    int s0 = blockIdx.x * 32, d0 = blockIdx.y * 32, h = blockIdx.z;
    int tx = threadIdx.x, ty = threadIdx.y;
    #pragma unroll
    for (int rr = 0; rr < 32; rr += 8)
        t[rr + ty][tx] = g_proj[(size_t)(s0 + rr + ty) * QKVN + 2 * HID + h * 128 + d0 + tx];
    __syncthreads();
    #pragma unroll
    for (int rr = 0; rr < 32; rr += 8) {
        int d = d0 + rr + ty;
        float v = t[tx][rr + ty];
        __nv_bfloat16 hi = __float2bfloat16(v);
        size_t o = ((size_t)h * 128 + d) * SEQ + s0 + tx;
        g_vth[o] = hi;
        g_vtl[o] = __float2bfloat16(v - __bfloat162float(hi));
    }
}

// ---------------- bf16x3 mma.sync flash attention (causal) — validated R5/R6 ----------
#define QPITCH 272
#define VPITCH 144
#define AT_QH  0
#define AT_QL  17408
#define AT_K0  34816
#define KV_KH  0
#define KV_KL  17408
#define KV_VH  34816
#define KV_VL  53248
#define AT_STAGE 71680
#define AT_SMEM  (AT_K0 + 2 * AT_STAGE)

__global__ __launch_bounds__(128, 1)
void attn_mma_kernel(float* __restrict__ out) {
    extern __shared__ char smraw[];
    const uint32_t sb = smem_to_u32(smraw);
    const int h  = blockIdx.x;
    const int qt = (int)gridDim.y - 1 - (int)blockIdx.y;
    const int tid = threadIdx.x, lane = tid & 31, warp = tid >> 5;
    const int wm16 = warp << 4;

    const __nv_bfloat16* qhp = g_qh + ((size_t)h * SEQ + qt * 64) * 128;
    const __nv_bfloat16* qlp = g_ql + ((size_t)h * SEQ + qt * 64) * 128;
    const __nv_bfloat16* kh0 = g_kh + (size_t)h * SEQ * 128;
    const __nv_bfloat16* kl0 = g_kl + (size_t)h * SEQ * 128;
    const __nv_bfloat16* vh0 = g_vth + (size_t)h * 128 * SEQ;
    const __nv_bfloat16* vl0 = g_vtl + (size_t)h * 128 * SEQ;

    auto load_kv = [&](int kt_, int buf_) {
        uint32_t base = sb + AT_K0 + (uint32_t)buf_ * AT_STAGE;
        const __nv_bfloat16* kh = kh0 + (size_t)kt_ * 64 * 128;
        const __nv_bfloat16* kl = kl0 + (size_t)kt_ * 64 * 128;
        #pragma unroll
        for (int u = 0; u < 16; u++) {
            int i = tid + u * 128;
            int m = i >> 10, c = i & 1023, r = c >> 4, seg = c & 15;
            cp_async16(base + m * 17408 + r * QPITCH + seg * 16,
                       (m ? kl : kh) + r * 128 + seg * 8);
        }
        const __nv_bfloat16* vh = vh0 + kt_ * 64;
        const __nv_bfloat16* vl = vl0 + kt_ * 64;
        #pragma unroll
        for (int u = 0; u < 16; u++) {
            int i = tid + u * 128;
            int m = i >> 10, c = i & 1023, r = c >> 3, seg = c & 7;
            cp_async16(base + KV_VH + m * 18432 + r * VPITCH + seg * 16,
                       (m ? vl : vh) + (size_t)r * SEQ + seg * 8);
        }
    };

    #pragma unroll
    for (int u = 0; u < 16; u++) {
        int i = tid + u * 128;
        int m = i >> 10, c = i & 1023, r = c >> 4, seg = c & 15;
        const __nv_bfloat16* src = m ? qlp : qhp;
        cp_async16(sb + (m ? AT_QL : AT_QH) + r * QPITCH + seg * 16,
                   src + r * 128 + seg * 8);
    }
    load_kv(0, 0);
    CP_COMMIT();

    float o[16][4];
    #pragma unroll
    for (int n = 0; n < 16; n++)
        #pragma unroll
        for (int e = 0; e < 4; e++) o[n][e] = 0.f;
    float m0 = neg_inf(), m1 = neg_inf(), l0 = 0.f, l1 = 0.f;

    for (int kt = 0; kt <= qt; kt++) {
        int buf = kt & 1;
        if (kt < qt) {
            load_kv(kt + 1, buf ^ 1);
            CP_COMMIT();
            CP_WAIT(1);
        } else {
            CP_WAIT(0);
        }
        __syncthreads();

        uint32_t kvb = sb + AT_K0 + (uint32_t)buf * AT_STAGE;

        float s4[8][4];
        #pragma unroll
        for (int j = 0; j < 8; j++)
            #pragma unroll
            for (int e = 0; e < 4; e++) s4[j][e] = 0.f;
        #pragma unroll
        for (int ks = 0; ks < 8; ks++) {
            uint32_t ah[4], al[4];
            uint32_t qa = (uint32_t)(wm16 + (lane & 15)) * QPITCH
                        + ks * 32 + ((lane >> 4) & 1) * 16;
            LDSM_X4(ah, sb + AT_QH + qa);
            LDSM_X4(al, sb + AT_QL + qa);
            #pragma unroll
            for (int j = 0; j < 8; j++) {
                uint32_t bh[2], bl[2];
                uint32_t ka = (uint32_t)(j * 8 + (lane & 7)) * QPITCH
                            + ks * 32 + ((lane >> 3) & 1) * 16;
                LDSM_X2(bh, kvb + KV_KH + ka);
                LDSM_X2(bl, kvb + KV_KL + ka);
                MMA_BF16(s4[j], ah, bh);
                MMA_BF16(s4[j], al, bh);
                MMA_BF16(s4[j], ah, bl);
            }
        }

        if (kt == qt) {
            int colb = 2 * (lane & 3);
            int rowb = wm16 + (lane >> 2);
            #pragma unroll
            for (int j = 0; j < 8; j++) {
                int c0 = j * 8 + colb;
                if (c0     > rowb)     s4[j][0] = neg_inf();
                if (c0 + 1 > rowb)     s4[j][1] = neg_inf();
                if (c0     > rowb + 8) s4[j][2] = neg_inf();
                if (c0 + 1 > rowb + 8) s4[j][3] = neg_inf();
            }
        }

        float tm0 = neg_inf(), tm1 = neg_inf();
        #pragma unroll
        for (int j = 0; j < 8; j++) {
            tm0 = fmaxf(tm0, fmaxf(s4[j][0], s4[j][1]));
            tm1 = fmaxf(tm1, fmaxf(s4[j][2], s4[j][3]));
        }
        tm0 = fmaxf(tm0, __shfl_xor_sync(0xffffffffu, tm0, 1));
        tm0 = fmaxf(tm0, __shfl_xor_sync(0xffffffffu, tm0, 2));
        tm1 = fmaxf(tm1, __shfl_xor_sync(0xffffffffu, tm1, 1));
        tm1 = fmaxf(tm1, __shfl_xor_sync(0xffffffffu, tm1, 2));
        float mn0 = fmaxf(m0, tm0), mn1 = fmaxf(m1, tm1);
        float a0 = __expf(m0 - mn0), a1 = __expf(m1 - mn1);
        m0 = mn0; m1 = mn1;

        float rs0 = 0.f, rs1 = 0.f;
        uint32_t pah[4][4], pal[4][4];
        #pragma unroll
        for (int j = 0; j < 8; j++) {
            float p0 = __expf(s4[j][0] - mn0), p1 = __expf(s4[j][1] - mn0);
            float p2 = __expf(s4[j][2] - mn1), p3 = __expf(s4[j][3] - mn1);
            rs0 += p0 + p1; rs1 += p2 + p3;
            __nv_bfloat16 b0 = __float2bfloat16(p0), b1 = __float2bfloat16(p1);
            __nv_bfloat16 b2 = __float2bfloat16(p2), b3 = __float2bfloat16(p3);
            uint32_t h01 = ((uint32_t)__bfloat16_as_ushort(b1) << 16) | __bfloat16_as_ushort(b0);
            uint32_t h23 = ((uint32_t)__bfloat16_as_ushort(b3) << 16) | __bfloat16_as_ushort(b2);
            __nv_bfloat16 c0 = __float2bfloat16(p0 - __bfloat162float(b0));
            __nv_bfloat16 c1 = __float2bfloat16(p1 - __bfloat162float(b1));
            __nv_bfloat16 c2 = __float2bfloat16(p2 - __bfloat162float(b2));
            __nv_bfloat16 c3 = __float2bfloat16(p3 - __bfloat162float(b3));
            uint32_t l01 = ((uint32_t)__bfloat16_as_ushort(c1) << 16) | __bfloat16_as_ushort(c0);
            uint32_t l23 = ((uint32_t)__bfloat16_as_ushort(c3) << 16) | __bfloat16_as_ushort(c2);
            int k2 = j >> 1, odd = (j & 1) << 1;
            pah[k2][odd] = h01; pah[k2][odd + 1] = h23;
            pal[k2][odd] = l01; pal[k2][odd + 1] = l23;
        }
        rs0 += __shfl_xor_sync(0xffffffffu, rs0, 1);
        rs0 += __shfl_xor_sync(0xffffffffu, rs0, 2);
        rs1 += __shfl_xor_sync(0xffffffffu, rs1, 1);
        rs1 += __shfl_xor_sync(0xffffffffu, rs1, 2);
        l0 = l0 * a0 + rs0;
        l1 = l1 * a1 + rs1;
        #pragma unroll
        for (int n = 0; n < 16; n++) {
            o[n][0] *= a0; o[n][1] *= a0; o[n][2] *= a1; o[n][3] *= a1;
        }

        #pragma unroll
        for (int ks2 = 0; ks2 < 4; ks2++) {
            #pragma unroll
            for (int n = 0; n < 16; n++) {
                uint32_t vh[2], vl[2];
                uint32_t va = (uint32_t)(n * 8 + (lane & 7)) * VPITCH
                            + ks2 * 32 + ((lane >> 3) & 1) * 16;
                LDSM_X2(vh, kvb + KV_VH + va);
                LDSM_X2(vl, kvb + KV_VL + va);
                MMA_BF16(o[n], pah[ks2], vh);
                MMA_BF16(o[n], pal[ks2], vh);
                MMA_BF16(o[n], pah[ks2], vl);
            }
        }
        __syncthreads();
    }

    float inv0 = 1.f / l0, inv1 = 1.f / l1;
    int rg = qt * 64 + wm16 + (lane >> 2);
    int cb = h * 128 + 2 * (lane & 3);
    #pragma unroll
    for (int n = 0; n < 16; n++) {
        float* p0 = out + (size_t)rg * HID + cb + n * 8;
        *(float2*)p0 = make_float2(o[n][0] * inv0, o[n][1] * inv0);
        float* p1 = out + (size_t)(rg + 8) * HID + cb + n * 8;
        *(float2*)p1 = make_float2(o[n][2] * inv1, o[n][3] * inv1);
    }
}

extern "C" void kernel_launch(void* const* d_in, const int* in_sizes, int n_in,
                              void* d_out, int out_size) {
    const float* hidden = (const float*)d_in[0];
    const int*   pos    = (const int*)d_in[1];
    const int*   qkv_qw = (const int*)d_in[2];
    const float* qkv_s  = (const float*)d_in[3];
    const float* qkv_z  = (const float*)d_in[4];
    const int*   o_qw   = (const int*)d_in[5];
    const float* o_s    = (const float*)d_in[6];
    const float* o_z    = (const float*)d_in[7];
    float* out = (float*)d_out;

    void* p;
    cudaGetSymbolAddress(&p, g_proj); float* proj = (float*)p;
    cudaGetSymbolAddress(&p, g_attn); float* attn = (float*)p;
    cudaGetSymbolAddress(&p, g_R);    float* R    = (float*)p;
    cudaGetSymbolAddress(&p, g_ah);   __half* ah  = (__half*)p;
    cudaGetSymbolAddress(&p, g_al);   __half* al  = (__half*)p;
    cudaGetSymbolAddress(&p, g_bq);   __half* bq  = (__half*)p;

    int gemm_smem = 3 * GSTAGE;                       // 98304
    cudaFuncSetAttribute(gemm_q_kernel,
                         cudaFuncAttributeMaxDynamicSharedMemorySize, gemm_smem);
    cudaFuncSetAttribute(attn_mma_kernel,
                         cudaFuncAttributeMaxDynamicSharedMemorySize, AT_SMEM);

    // 1. RoPE tables
    rope_tables_kernel<<<SEQ, 64>>>(pos);

    // 2. prep: activations (hi/lo + group rowsums), exact-q weights, scales
    split_pad_kernel<<<(SEQ * HID) / (256 * 4), 256>>>(hidden, ah, al);
    rowsum_ext_kernel<<<SEQ, 256>>>(hidden, ah, al);
    qT_kernel<<<dim3(QKVN / 32, HID / 32), 256>>>(qkv_qw, bq, QKVN);
    prep_scales_kernel<<<QKVN / 256, 256>>>(qkv_s, qkv_z, R, bq, QKVN);

    // 3. QKV projection (exact-q GEMM)
    gemm_q_kernel<<<dim3(SEQ / 128, QKVN / 256), 256, gemm_smem>>>(
        ah, al, bq, R, proj, SEQ, QKVN);

    // 4. RoPE + split Q/K; transpose + split V
    rope_split_kernel<<<SEQ, 256>>>();
    v_transpose_split_kernel<<<dim3(SEQ / 32, HDIM / 32, HEADS), dim3(32, 8)>>>();

    // 5. causal flash attention
    attn_mma_kernel<<<dim3(HEADS, SEQ / 64), 128, AT_SMEM>>>(attn);

    // 6. prep for O projection (reuse ah/al/bq/R)
    split_pad_kernel<<<(SEQ * HID) / (256 * 4), 256>>>(attn, ah, al);
    rowsum_ext_kernel<<<SEQ, 256>>>(attn, ah, al);
    qT_kernel<<<dim3(HID / 32, HID / 32), 256>>>(o_qw, bq, HID);
    prep_scales_kernel<<<HID / 256, 256>>>(o_s, o_z, R, bq, HID);

    // 7. output projection
    gemm_q_kernel<<<dim3(SEQ / 128, HID / 256), 256, gemm_smem>>>(
        ah, al, bq, R, out, SEQ, HID);
}